// round 10
// baseline (speedup 1.0000x reference)
#include <cuda_runtime.h>
#include <math.h>

// ---------------- problem constants ----------------
#define NB    64        // batch
#define NN    1000      // nodes per sample
#define NTOT  64000     // NB*NN
#define SEQL  12
#define D1    4000      // NN*FEAT
#define H1S   256
#define H2S   128
#define G1    1024      // 4*H1S
#define G2    512       // 4*H2S
#define TBR   768       // SEQL*NB
#define EMAX  1024000
#define ETOTMAX (EMAX + NTOT)
#define SPLITK 5        // K=4000 -> klen=800, multiple of 16

typedef unsigned long long ull;

// ---------------- scratch (device globals; no allocation allowed) ----------------
__device__ __align__(256) float d_h[NTOT * 96];        // GAT hidden, [n][head][c]
__device__ __align__(256) float d_asrc[NTOT * 2];
__device__ __align__(256) float d_adst[NTOT * 2];
__device__ __align__(256) float d_m[NTOT * 2];         // segment max
__device__ __align__(256) float d_den[NTOT * 2];       // segment sum -> 0.5/(den+eps)
__device__ __align__(256) float d_w[ETOTMAX * 2];      // leaky value -> softmax numerator
__device__ __align__(256) float d_g[NTOT * 48];        // GAT output (head-mean, no bias)
__device__ __align__(256) float d_xw1[TBR * G1];       // LSTM1 input projection
__device__ __align__(256) float d_whh1T[H1S * G1];
__device__ __align__(256) float d_whh2T[H2S * G2];
__device__ __align__(256) float d_wih2T[H1S * G2];
__device__ __align__(256) float d_ws[G1 * 4];          // col-sums of W_ih1 per (j, f)

// ---------------- helpers ----------------
__device__ __forceinline__ float sigf(float x) { return 1.f / (1.f + expf(-x)); }

__device__ __forceinline__ void atomicMaxF(float* addr, float v) {
    if (v >= 0.f) atomicMax((int*)addr, __float_as_int(v));
    else          atomicMin((unsigned int*)addr, __float_as_uint(v));
}

// packed f32x2 FMA (FFMA2)
__device__ __forceinline__ void fma2(ull& acc, ull a, ull b) {
    asm("fma.rn.f32x2 %0, %1, %2, %0;" : "+l"(acc) : "l"(a), "l"(b));
}
__device__ __forceinline__ ull pack2(float x, float y) {
    ull r; asm("mov.b64 %0, {%1, %2};" : "=l"(r) : "f"(x), "f"(y)); return r;
}
__device__ __forceinline__ float2 unpack2(ull v) {
    float2 r; asm("mov.b64 {%0, %1}, %2;" : "=f"(r.x), "=f"(r.y) : "l"(v)); return r;
}
__device__ __forceinline__ void redv4(float* dst, float a, float b, float c, float d) {
    asm volatile("red.global.add.v4.f32 [%0], {%1, %2, %3, %4};"
                 :: "l"(dst), "f"(a), "f"(b), "f"(c), "f"(d) : "memory");
}

// ---------------- kernels ----------------
__global__ void k_init() {
    int idx = blockIdx.x * blockDim.x + threadIdx.x;
    if (idx < NTOT * 48) d_g[idx] = 0.f;
    if (idx < NTOT * 2) { d_m[idx] = __int_as_float(0xff800000); d_den[idx] = 0.f; }
}

// ws[j, f] = sum_n W_ih1[j, 4n+f] ; one block per j, 128 threads
__global__ void k_wsum(const float* __restrict__ W) {
    __shared__ float part[128];
    int j = blockIdx.x;
    const float* wr = W + (size_t)j * D1;
    float acc = 0.f;
    for (int e = threadIdx.x; e < D1; e += 128) acc += __ldg(wr + e);   // f = e&3 fixed per thread
    part[threadIdx.x] = acc;
    __syncthreads();
    if (threadIdx.x < 4) {
        float s = 0.f;
        for (int i = threadIdx.x; i < 128; i += 4) s += part[i];
        d_ws[j * 4 + threadIdx.x] = s;
    }
}

// d_xw1[(t*NB+b)*G1 + j] = b1[j] + sum_f gbias[4t+f] * ws[j,f]
__global__ void k_biasinit(const float* __restrict__ b1, const float* __restrict__ gbias) {
    int idx = blockIdx.x * blockDim.x + threadIdx.x;
    if (idx >= TBR * G1) return;
    int j = idx & (G1 - 1);
    int t = idx / (G1 * NB);
    float v = __ldg(b1 + j);
#pragma unroll
    for (int f = 0; f < 4; f++) v = fmaf(__ldg(gbias + t * 4 + f), d_ws[j * 4 + f], v);
    d_xw1[idx] = v;
}

// h[n, j2:j2+2] = sum_k x[n,k] * Wg[k, j2:j2+2]   (f32x2)
__global__ void k_gemm_h(const float* __restrict__ x, const float* __restrict__ Wg) {
    __shared__ __align__(16) float ws[48 * 96];
    for (int i = threadIdx.x; i < 48 * 96; i += blockDim.x) ws[i] = Wg[i];
    __syncthreads();
    int idx = blockIdx.x * blockDim.x + threadIdx.x;
    if (idx >= NTOT * 48) return;
    int n = idx / 48, j2 = (idx % 48) * 2;
    const float* xr = x + (size_t)n * 48;
    ull acc = 0;
#pragma unroll
    for (int k = 0; k < 48; k++) {
        float xv = __ldg(xr + k);
        fma2(acc, pack2(xv, xv), *(const ull*)(ws + k * 96 + j2));
    }
    float2 u = unpack2(acc);
    *(float2*)(d_h + (size_t)n * 96 + j2) = u;
}

__global__ void k_attn(const float* __restrict__ att_s, const float* __restrict__ att_d) {
    int idx = blockIdx.x * blockDim.x + threadIdx.x;
    if (idx >= NTOT * 2) return;
    int n = idx >> 1, hd = idx & 1;
    const float* hr = d_h + (size_t)n * 96 + hd * 48;
    float s1 = 0.f, s2 = 0.f;
#pragma unroll
    for (int c = 0; c < 48; c++) {
        float hv = hr[c];
        s1 = fmaf(hv, __ldg(att_s + hd * 48 + c), s1);
        s2 = fmaf(hv, __ldg(att_d + hd * 48 + c), s2);
    }
    d_asrc[idx] = s1;
    d_adst[idx] = s2;
}

// edge_index arrives as int32 (JAX x64 disabled)
__device__ __forceinline__ void edge_sd(const int* __restrict__ ei, int E, int e,
                                        int& s, int& d) {
    if (e < E) { s = ei[e]; d = ei[E + e]; }
    else       { s = e - E; d = s; }
}

// compute leaky value v, store to d_w, atomicMax into d_m
__global__ void k_passA(const int* __restrict__ ei, int E) {
    int idx = blockIdx.x * blockDim.x + threadIdx.x;
    int etot = E + NTOT;
    if (idx >= etot * 2) return;
    int e = idx >> 1, hd = idx & 1;
    int s, d; edge_sd(ei, E, e, s, d);
    float v = d_asrc[s * 2 + hd] + d_adst[d * 2 + hd];
    v = v > 0.f ? v : 0.2f * v;
    d_w[idx] = v;
    atomicMaxF(&d_m[d * 2 + hd], v);
}

// w = exp(v - m[d]); store; accumulate den
__global__ void k_passB(const int* __restrict__ ei, int E) {
    int idx = blockIdx.x * blockDim.x + threadIdx.x;
    int etot = E + NTOT;
    if (idx >= etot * 2) return;
    int e = idx >> 1, hd = idx & 1;
    int d = (e < E) ? ei[E + e] : (e - E);
    float w = expf(d_w[idx] - d_m[d * 2 + hd]);
    d_w[idx] = w;
    atomicAdd(&d_den[d * 2 + hd], w);
}

// d_den := 0.5/(den+eps)  (0.5 = head-mean folded in)
__global__ void k_inv() {
    int idx = blockIdx.x * blockDim.x + threadIdx.x;
    if (idx >= NTOT * 2) return;
    d_den[idx] = 0.5f / (d_den[idx] + 1e-16f);
}

// g[dst, q*4:+4] += a0*inv0*h[src,0,...] + a1*inv1*h[src,1,...]
__global__ void k_passC(const int* __restrict__ ei, int E) {
    int idx = blockIdx.x * blockDim.x + threadIdx.x;
    int etot = E + NTOT;
    if (idx >= etot * 12) return;
    int e = idx / 12, q = idx - e * 12;
    int s, d; edge_sd(ei, E, e, s, d);
    float2 a   = *(const float2*)(d_w + (size_t)e * 2);
    float2 inv = *(const float2*)(d_den + (size_t)d * 2);
    float a0 = a.x * inv.x, a1 = a.y * inv.y;
    const float4 h0 = *(const float4*)(d_h + (size_t)s * 96 + q * 4);
    const float4 h1 = *(const float4*)(d_h + (size_t)s * 96 + 48 + q * 4);
    float vx = fmaf(a0, h0.x, a1 * h1.x);
    float vy = fmaf(a0, h0.y, a1 * h1.y);
    float vz = fmaf(a0, h0.z, a1 * h1.z);
    float vw = fmaf(a0, h0.w, a1 * h1.w);
    redv4(d_g + (size_t)d * 48 + q * 4, vx, vy, vz, vw);
}

// NT SGEMM, A read directly from d_g (reshape folded into indexing).
// C = d_xw1 (pre-init'd with bias+WS), split-K via blockIdx.z, red-v4 epilogue.
// m = t*64+b ; blockIdx.y == t ; A[m][k] = g[(b*1000 + k/4)*48 + 4t + k%4]
__global__ void k_sgemm1(const float* __restrict__ B) {
    const int K = D1, N = G1;
    __shared__ __align__(16) float As[16][64];
    __shared__ __align__(16) float Bs[16][64];
    int t = threadIdx.x;
    int ty = t >> 3;              // 0..15
    int tx = t & 7;               // 0..7
    int tq = blockIdx.y * 4;      // 4*t (time index * FEAT)
    int m0 = blockIdx.y * 64;
    int n0 = blockIdx.x * 64;
    int klen = K / SPLITK;        // 800
    int kbeg = blockIdx.z * klen;

    ull acc2[4][4];
#pragma unroll
    for (int i = 0; i < 4; i++)
#pragma unroll
        for (int j = 0; j < 4; j++) acc2[i][j] = 0ULL;

    for (int k0 = kbeg; k0 < kbeg + klen; k0 += 16) {
#pragma unroll
        for (int l = 0; l < 2; l++) {
            int lin = t + l * 128;        // 0..255
            int mm = lin & 63;
            int kk4 = lin >> 6;           // 0..3
            float4 av = *(const float4*)(d_g + ((size_t)mm * NN + (k0 >> 2) + kk4) * 48 + tq);
            As[kk4 * 4 + 0][mm] = av.x; As[kk4 * 4 + 1][mm] = av.y;
            As[kk4 * 4 + 2][mm] = av.z; As[kk4 * 4 + 3][mm] = av.w;
            float4 bv = *(const float4*)(B + (size_t)(n0 + mm) * K + k0 + kk4 * 4);
            Bs[kk4 * 4 + 0][mm] = bv.x; Bs[kk4 * 4 + 1][mm] = bv.y;
            Bs[kk4 * 4 + 2][mm] = bv.z; Bs[kk4 * 4 + 3][mm] = bv.w;
        }
        __syncthreads();
#pragma unroll
        for (int kk = 0; kk < 16; kk++) {
            float4 a = *(const float4*)&As[kk][ty * 4];
            ull ad0 = pack2(a.x, a.x), ad1 = pack2(a.y, a.y);
            ull ad2 = pack2(a.z, a.z), ad3 = pack2(a.w, a.w);
            const ull* bp = (const ull*)&Bs[kk][tx * 8];
            ull b0 = bp[0], b1 = bp[1], b2 = bp[2], b3 = bp[3];
            fma2(acc2[0][0], ad0, b0); fma2(acc2[0][1], ad0, b1);
            fma2(acc2[0][2], ad0, b2); fma2(acc2[0][3], ad0, b3);
            fma2(acc2[1][0], ad1, b0); fma2(acc2[1][1], ad1, b1);
            fma2(acc2[1][2], ad1, b2); fma2(acc2[1][3], ad1, b3);
            fma2(acc2[2][0], ad2, b0); fma2(acc2[2][1], ad2, b1);
            fma2(acc2[2][2], ad2, b2); fma2(acc2[2][3], ad2, b3);
            fma2(acc2[3][0], ad3, b0); fma2(acc2[3][1], ad3, b1);
            fma2(acc2[3][2], ad3, b2); fma2(acc2[3][3], ad3, b3);
        }
        __syncthreads();
    }
#pragma unroll
    for (int i = 0; i < 4; i++) {
        int m = m0 + ty * 4 + i;
        float* cr = d_xw1 + (size_t)m * N + n0 + tx * 8;
        float2 u0 = unpack2(acc2[i][0]), u1 = unpack2(acc2[i][1]);
        float2 u2 = unpack2(acc2[i][2]), u3 = unpack2(acc2[i][3]);
        redv4(cr,     u0.x, u0.y, u1.x, u1.y);
        redv4(cr + 4, u2.x, u2.y, u3.x, u3.y);
    }
}

// WT[k*G + j] = W[j*Hs + k]
__global__ void k_transpose(int which, const float* __restrict__ W) {
    int G  = (which == 1) ? G1 : G2;
    int Hs = (which == 2) ? H2S : H1S;
    float* WT = (which == 1) ? d_whh1T : (which == 2) ? d_whh2T : d_wih2T;
    int idx = blockIdx.x * blockDim.x + threadIdx.x;
    if (idx >= G * Hs) return;
    int k = idx / G, j = idx % G;
    WT[idx] = W[(size_t)j * Hs + k];
}

// ============ fused LSTM (both layers, all 12 steps) + output linear ============
// 32 blocks x 256 threads; block handles batches b0=2*blk, b0+1.
// h/c state lives in smem/regs across the whole sequence. No grid sync needed:
// the recurrence is batch-parallel.
__global__ __launch_bounds__(256) void k_lstm_fused(
    const float* __restrict__ b2v, const float* __restrict__ Wo,
    const float* __restrict__ bo, float* __restrict__ out)
{
    __shared__ __align__(16) ull hb[2][H1S];    // h1 duplicated-pair per batch
    __shared__ __align__(16) ull hb2[2][H2S];   // h2 duplicated-pair per batch
    __shared__ __align__(16) ull hmix[H2S];     // (h2[b0,k], h2[b1,k])
    __shared__ __align__(16) float gsm[2][G1];  // gate staging

    int tid = threadIdx.x;
    int b0 = blockIdx.x * 2;

    if (tid < H1S) { hb[0][tid] = 0ULL; hb[1][tid] = 0ULL; }
    if (tid < H2S) { hb2[0][tid] = 0ULL; hb2[1][tid] = 0ULL; }
    float c1a = 0.f, c1b = 0.f;          // c1[u=tid]
    float c2a = 0.f, c2b = 0.f;          // c2[u=tid], tid<128
    __syncthreads();

    for (int t = 0; t < SEQL; t++) {
        // ---- layer1 gates: thread handles j0..j0+3 ----
        {
            int j0 = tid * 4;
            ull aA = 0, aB = 0, aC = 0, aD = 0;
#pragma unroll 4
            for (int k = 0; k < H1S; k++) {
                ulonglong2 w = *(const ulonglong2*)(d_whh1T + (size_t)k * G1 + j0);
                ull h0 = hb[0][k], h1v = hb[1][k];
                fma2(aA, w.x, h0);  fma2(aB, w.y, h0);
                fma2(aC, w.x, h1v); fma2(aD, w.y, h1v);
            }
            float4 xa = *(const float4*)(d_xw1 + ((size_t)(t * NB + b0)) * G1 + j0);
            float4 xb = *(const float4*)(d_xw1 + ((size_t)(t * NB + b0 + 1)) * G1 + j0);
            float2 uA = unpack2(aA), uB = unpack2(aB), uC = unpack2(aC), uD = unpack2(aD);
            *(float4*)&gsm[0][j0] = make_float4(uA.x + xa.x, uA.y + xa.y, uB.x + xa.z, uB.y + xa.w);
            *(float4*)&gsm[1][j0] = make_float4(uC.x + xb.x, uC.y + xb.y, uD.x + xb.z, uD.y + xb.w);
        }
        __syncthreads();
        // ---- layer1 elementwise: u = tid (PyTorch i,f,g,o order) ----
        {
            int u = tid;
            float i0 = sigf(gsm[0][u]),        f0 = sigf(gsm[0][H1S + u]);
            float g0 = tanhf(gsm[0][2 * H1S + u]), o0 = sigf(gsm[0][3 * H1S + u]);
            c1a = f0 * c1a + i0 * g0;
            float hA = o0 * tanhf(c1a);
            float i1 = sigf(gsm[1][u]),        f1 = sigf(gsm[1][H1S + u]);
            float g1 = tanhf(gsm[1][2 * H1S + u]), o1 = sigf(gsm[1][3 * H1S + u]);
            c1b = f1 * c1b + i1 * g1;
            float hB = o1 * tanhf(c1b);
            hb[0][u] = pack2(hA, hA);
            hb[1][u] = pack2(hB, hB);
        }
        __syncthreads();
        // ---- layer2 gates: thread handles j pair (2tid, 2tid+1) ----
        {
            int j = tid * 2;
            ull aA = 0, aB = 0;
#pragma unroll 4
            for (int k = 0; k < H1S; k++) {
                ull w = *(const ull*)(d_wih2T + (size_t)k * G2 + j);
                fma2(aA, w, hb[0][k]);
                fma2(aB, w, hb[1][k]);
            }
#pragma unroll 4
            for (int k = 0; k < H2S; k++) {
                ull w = *(const ull*)(d_whh2T + (size_t)k * G2 + j);
                fma2(aA, w, hb2[0][k]);
                fma2(aB, w, hb2[1][k]);
            }
            float2 bb = *(const float2*)(b2v + j);
            float2 uA = unpack2(aA), uB = unpack2(aB);
            *(float2*)&gsm[0][j] = make_float2(uA.x + bb.x, uA.y + bb.y);
            *(float2*)&gsm[1][j] = make_float2(uB.x + bb.x, uB.y + bb.y);
        }
        __syncthreads();
        // ---- layer2 elementwise: u = tid < 128 ----
        if (tid < H2S) {
            int u = tid;
            float i0 = sigf(gsm[0][u]),        f0 = sigf(gsm[0][H2S + u]);
            float g0 = tanhf(gsm[0][2 * H2S + u]), o0 = sigf(gsm[0][3 * H2S + u]);
            c2a = f0 * c2a + i0 * g0;
            float hA = o0 * tanhf(c2a);
            float i1 = sigf(gsm[1][u]),        f1 = sigf(gsm[1][H2S + u]);
            float g1 = tanhf(gsm[1][2 * H2S + u]), o1 = sigf(gsm[1][3 * H2S + u]);
            c2b = f1 * c2b + i1 * g1;
            float hB = o1 * tanhf(c2b);
            hb2[0][u] = pack2(hA, hA);
            hb2[1][u] = pack2(hB, hB);
            hmix[u]   = pack2(hA, hB);
        }
        __syncthreads();
    }

    // ---- output linear: out[b, jj] = Wo[jj,:]·h2[b] + bo[jj] ----
    for (int jj = tid; jj < NN * 2; jj += 256) {
        const float* wr = Wo + (size_t)jj * H2S;
        ull acc = 0;
#pragma unroll 4
        for (int k = 0; k < H2S; k++) {
            float w = __ldg(wr + k);
            fma2(acc, pack2(w, w), hmix[k]);
        }
        float2 u = unpack2(acc);
        float bv = __ldg(bo + jj);
        out[(size_t)b0 * (NN * 2) + jj]       = u.x + bv;
        out[(size_t)(b0 + 1) * (NN * 2) + jj] = u.y + bv;
    }
}

// ---------------- launch ----------------
extern "C" void kernel_launch(void* const* d_in, const int* in_sizes, int n_in,
                              void* d_out, int out_size) {
    const float* x     = (const float*)d_in[0];
    const int*   ei    = (const int*)d_in[1];     // int32 (JAX x64 disabled)
    const float* Wg    = (const float*)d_in[2];
    const float* att_s = (const float*)d_in[3];
    const float* att_d = (const float*)d_in[4];
    const float* gbias = (const float*)d_in[5];
    const float* Wih1  = (const float*)d_in[6];
    const float* Whh1  = (const float*)d_in[7];
    const float* b1    = (const float*)d_in[8];
    const float* Wih2  = (const float*)d_in[9];
    const float* Whh2  = (const float*)d_in[10];
    const float* b2    = (const float*)d_in[11];
    const float* Wo    = (const float*)d_in[12];
    const float* bo    = (const float*)d_in[13];
    float* out = (float*)d_out;

    int E = in_sizes[1] / 2;
    if (E > EMAX) E = EMAX;
    int etot = E + NTOT;

    k_init<<<(NTOT * 48 + 255) / 256, 256>>>();
    k_gemm_h<<<(NTOT * 48 + 255) / 256, 256>>>(x, Wg);
    k_wsum<<<G1, 128>>>(Wih1);
    k_biasinit<<<(TBR * G1 + 255) / 256, 256>>>(b1, gbias);
    k_transpose<<<(H1S * G1 + 255) / 256, 256>>>(1, Whh1);
    k_transpose<<<(H2S * G2 + 255) / 256, 256>>>(2, Whh2);
    k_transpose<<<(H1S * G2 + 255) / 256, 256>>>(3, Wih2);
    k_attn<<<(NTOT * 2 + 255) / 256, 256>>>(att_s, att_d);
    k_passA<<<(etot * 2 + 255) / 256, 256>>>(ei, E);
    k_passB<<<(etot * 2 + 255) / 256, 256>>>(ei, E);
    k_inv<<<(NTOT * 2 + 255) / 256, 256>>>();
    k_passC<<<(etot * 12 + 255) / 256, 256>>>(ei, E);

    k_sgemm1<<<dim3(G1 / 64, SEQL, SPLITK), 128>>>(Wih1);
    k_lstm_fused<<<NB / 2, 256>>>(b2, Wo, bo, out);
}

// round 11
// speedup vs baseline: 1.0963x; 1.0963x over previous
#include <cuda_runtime.h>
#include <math.h>

// ---------------- problem constants ----------------
#define NB    64        // batch
#define NN    1000      // nodes per sample
#define NTOT  64000     // NB*NN
#define SEQL  12
#define D1    4000      // NN*FEAT
#define H1S   256
#define H2S   128
#define G1    1024      // 4*H1S
#define G2    512       // 4*H2S
#define TBR   768       // SEQL*NB
#define EMAX  1024000
#define ETOTMAX (EMAX + NTOT)
#define SPLITK 5        // K=4000 -> klen=800, multiple of 16

typedef unsigned long long ull;

// ---------------- scratch (device globals; no allocation allowed) ----------------
__device__ __align__(256) float d_h[NTOT * 96];        // GAT hidden, [n][head][c]
__device__ __align__(256) float d_asrc[NTOT * 2];
__device__ __align__(256) float d_adst[NTOT * 2];
__device__ __align__(256) float d_m[NTOT * 2];         // segment max
__device__ __align__(256) float d_den[NTOT * 2];       // segment sum
__device__ __align__(256) float d_w[ETOTMAX * 2];      // leaky value -> softmax numerator
__device__ __align__(256) float d_g[NTOT * 48];        // GAT output (head-mean, no bias)
__device__ __align__(256) float d_xw1[TBR * G1];       // LSTM1 input projection
__device__ __align__(256) float d_whh1T[H1S * G1];
__device__ __align__(256) float d_whh2T[H2S * G2];
__device__ __align__(256) float d_wih2T[H1S * G2];
__device__ __align__(256) float d_ws[G1 * 4];          // col-sums of W_ih1 per (j, f)

// ---------------- helpers ----------------
__device__ __forceinline__ float sigf(float x) { return 1.f / (1.f + expf(-x)); }

__device__ __forceinline__ void atomicMaxF(float* addr, float v) {
    if (v >= 0.f) atomicMax((int*)addr, __float_as_int(v));
    else          atomicMin((unsigned int*)addr, __float_as_uint(v));
}

// packed f32x2 FMA (FFMA2)
__device__ __forceinline__ void fma2(ull& acc, ull a, ull b) {
    asm("fma.rn.f32x2 %0, %1, %2, %0;" : "+l"(acc) : "l"(a), "l"(b));
}
__device__ __forceinline__ ull pack2(float x, float y) {
    ull r; asm("mov.b64 %0, {%1, %2};" : "=l"(r) : "f"(x), "f"(y)); return r;
}
__device__ __forceinline__ float2 unpack2(ull v) {
    float2 r; asm("mov.b64 {%0, %1}, %2;" : "=f"(r.x), "=f"(r.y) : "l"(v)); return r;
}
__device__ __forceinline__ void redv4(float* dst, float a, float b, float c, float d) {
    asm volatile("red.global.add.v4.f32 [%0], {%1, %2, %3, %4};"
                 :: "l"(dst), "f"(a), "f"(b), "f"(c), "f"(d) : "memory");
}

// ---------------- kernels ----------------
__global__ void k_init() {
    int idx = blockIdx.x * blockDim.x + threadIdx.x;
    if (idx < NTOT * 48) d_g[idx] = 0.f;
    if (idx < NTOT * 2) { d_m[idx] = __int_as_float(0xff800000); d_den[idx] = 0.f; }
}

// ws[j, f] = sum_n W_ih1[j, 4n+f] ; one block per j, 128 threads
__global__ void k_wsum(const float* __restrict__ W) {
    __shared__ float part[128];
    int j = blockIdx.x;
    const float* wr = W + (size_t)j * D1;
    float acc = 0.f;
    for (int e = threadIdx.x; e < D1; e += 128) acc += __ldg(wr + e);   // f = e&3 fixed per thread
    part[threadIdx.x] = acc;
    __syncthreads();
    if (threadIdx.x < 4) {
        float s = 0.f;
        for (int i = threadIdx.x; i < 128; i += 4) s += part[i];
        d_ws[j * 4 + threadIdx.x] = s;
    }
}

// d_xw1[(t*NB+b)*G1 + j] = b1[j] + sum_f gbias[4t+f] * ws[j,f]
__global__ void k_biasinit(const float* __restrict__ b1, const float* __restrict__ gbias) {
    int idx = blockIdx.x * blockDim.x + threadIdx.x;
    if (idx >= TBR * G1) return;
    int j = idx & (G1 - 1);
    int t = idx / (G1 * NB);
    float v = __ldg(b1 + j);
#pragma unroll
    for (int f = 0; f < 4; f++) v = fmaf(__ldg(gbias + t * 4 + f), d_ws[j * 4 + f], v);
    d_xw1[idx] = v;
}

// h[n, j2:j2+2] = sum_k x[n,k] * Wg[k, j2:j2+2]   (f32x2)
__global__ void k_gemm_h(const float* __restrict__ x, const float* __restrict__ Wg) {
    __shared__ __align__(16) float ws[48 * 96];
    for (int i = threadIdx.x; i < 48 * 96; i += blockDim.x) ws[i] = Wg[i];
    __syncthreads();
    int idx = blockIdx.x * blockDim.x + threadIdx.x;
    if (idx >= NTOT * 48) return;
    int n = idx / 48, j2 = (idx % 48) * 2;
    const float* xr = x + (size_t)n * 48;
    ull acc = 0;
#pragma unroll
    for (int k = 0; k < 48; k++) {
        float xv = __ldg(xr + k);
        fma2(acc, pack2(xv, xv), *(const ull*)(ws + k * 96 + j2));
    }
    float2 u = unpack2(acc);
    *(float2*)(d_h + (size_t)n * 96 + j2) = u;
}

__global__ void k_attn(const float* __restrict__ att_s, const float* __restrict__ att_d) {
    int idx = blockIdx.x * blockDim.x + threadIdx.x;
    if (idx >= NTOT * 2) return;
    int n = idx >> 1, hd = idx & 1;
    const float* hr = d_h + (size_t)n * 96 + hd * 48;
    float s1 = 0.f, s2 = 0.f;
#pragma unroll
    for (int c = 0; c < 48; c++) {
        float hv = hr[c];
        s1 = fmaf(hv, __ldg(att_s + hd * 48 + c), s1);
        s2 = fmaf(hv, __ldg(att_d + hd * 48 + c), s2);
    }
    d_asrc[idx] = s1;
    d_adst[idx] = s2;
}

// edge_index arrives as int32 (JAX x64 disabled)
__device__ __forceinline__ void edge_sd(const int* __restrict__ ei, int E, int e,
                                        int& s, int& d) {
    if (e < E) { s = ei[e]; d = ei[E + e]; }
    else       { s = e - E; d = s; }
}

// compute leaky value v, store to d_w, atomicMax into d_m
__global__ void k_passA(const int* __restrict__ ei, int E) {
    int idx = blockIdx.x * blockDim.x + threadIdx.x;
    int etot = E + NTOT;
    if (idx >= etot * 2) return;
    int e = idx >> 1, hd = idx & 1;
    int s, d; edge_sd(ei, E, e, s, d);
    float v = d_asrc[s * 2 + hd] + d_adst[d * 2 + hd];
    v = v > 0.f ? v : 0.2f * v;
    d_w[idx] = v;
    atomicMaxF(&d_m[d * 2 + hd], v);
}

// w = exp(v - m[d]); store; accumulate den
__global__ void k_passB(const int* __restrict__ ei, int E) {
    int idx = blockIdx.x * blockDim.x + threadIdx.x;
    int etot = E + NTOT;
    if (idx >= etot * 2) return;
    int e = idx >> 1, hd = idx & 1;
    int d = (e < E) ? ei[E + e] : (e - E);
    float w = expf(d_w[idx] - d_m[d * 2 + hd]);
    d_w[idx] = w;
    atomicAdd(&d_den[d * 2 + hd], w);
}

// g[dst, q*4:+4] += a0*h[src,0,...] + a1*h[src,1,...]
// normalization (0.5/(den+eps)) computed inline (fast division; den >= 1)
__global__ void k_passC(const int* __restrict__ ei, int E) {
    int idx = blockIdx.x * blockDim.x + threadIdx.x;
    int etot = E + NTOT;
    if (idx >= etot * 12) return;
    int e = idx / 12, q = idx - e * 12;
    int s, d; edge_sd(ei, E, e, s, d);
    float2 a  = *(const float2*)(d_w + (size_t)e * 2);
    float2 dn = *(const float2*)(d_den + (size_t)d * 2);
    float a0 = a.x * __fdividef(0.5f, dn.x + 1e-16f);
    float a1 = a.y * __fdividef(0.5f, dn.y + 1e-16f);
    const float4 h0 = *(const float4*)(d_h + (size_t)s * 96 + q * 4);
    const float4 h1 = *(const float4*)(d_h + (size_t)s * 96 + 48 + q * 4);
    float vx = fmaf(a0, h0.x, a1 * h1.x);
    float vy = fmaf(a0, h0.y, a1 * h1.y);
    float vz = fmaf(a0, h0.z, a1 * h1.z);
    float vw = fmaf(a0, h0.w, a1 * h1.w);
    redv4(d_g + (size_t)d * 48 + q * 4, vx, vy, vz, vw);
}

// NT SGEMM, A read directly from d_g (reshape folded into indexing).
// C = d_xw1 (pre-init'd with bias+WS), split-K via blockIdx.z, red-v4 epilogue.
__global__ void k_sgemm1(const float* __restrict__ B) {
    const int K = D1, N = G1;
    __shared__ __align__(16) float As[16][64];
    __shared__ __align__(16) float Bs[16][64];
    int t = threadIdx.x;
    int ty = t >> 3;              // 0..15
    int tx = t & 7;               // 0..7
    int tq = blockIdx.y * 4;      // 4*t (time index * FEAT)
    int m0 = blockIdx.y * 64;
    int n0 = blockIdx.x * 64;
    int klen = K / SPLITK;        // 800
    int kbeg = blockIdx.z * klen;

    ull acc2[4][4];
#pragma unroll
    for (int i = 0; i < 4; i++)
#pragma unroll
        for (int j = 0; j < 4; j++) acc2[i][j] = 0ULL;

    for (int k0 = kbeg; k0 < kbeg + klen; k0 += 16) {
#pragma unroll
        for (int l = 0; l < 2; l++) {
            int lin = t + l * 128;        // 0..255
            int mm = lin & 63;
            int kk4 = lin >> 6;           // 0..3
            float4 av = *(const float4*)(d_g + ((size_t)mm * NN + (k0 >> 2) + kk4) * 48 + tq);
            As[kk4 * 4 + 0][mm] = av.x; As[kk4 * 4 + 1][mm] = av.y;
            As[kk4 * 4 + 2][mm] = av.z; As[kk4 * 4 + 3][mm] = av.w;
            float4 bv = *(const float4*)(B + (size_t)(n0 + mm) * K + k0 + kk4 * 4);
            Bs[kk4 * 4 + 0][mm] = bv.x; Bs[kk4 * 4 + 1][mm] = bv.y;
            Bs[kk4 * 4 + 2][mm] = bv.z; Bs[kk4 * 4 + 3][mm] = bv.w;
        }
        __syncthreads();
#pragma unroll
        for (int kk = 0; kk < 16; kk++) {
            float4 a = *(const float4*)&As[kk][ty * 4];
            ull ad0 = pack2(a.x, a.x), ad1 = pack2(a.y, a.y);
            ull ad2 = pack2(a.z, a.z), ad3 = pack2(a.w, a.w);
            const ull* bp = (const ull*)&Bs[kk][tx * 8];
            ull b0 = bp[0], b1 = bp[1], b2 = bp[2], b3 = bp[3];
            fma2(acc2[0][0], ad0, b0); fma2(acc2[0][1], ad0, b1);
            fma2(acc2[0][2], ad0, b2); fma2(acc2[0][3], ad0, b3);
            fma2(acc2[1][0], ad1, b0); fma2(acc2[1][1], ad1, b1);
            fma2(acc2[1][2], ad1, b2); fma2(acc2[1][3], ad1, b3);
            fma2(acc2[2][0], ad2, b0); fma2(acc2[2][1], ad2, b1);
            fma2(acc2[2][2], ad2, b2); fma2(acc2[2][3], ad2, b3);
            fma2(acc2[3][0], ad3, b0); fma2(acc2[3][1], ad3, b1);
            fma2(acc2[3][2], ad3, b2); fma2(acc2[3][3], ad3, b3);
        }
        __syncthreads();
    }
#pragma unroll
    for (int i = 0; i < 4; i++) {
        int m = m0 + ty * 4 + i;
        float* cr = d_xw1 + (size_t)m * N + n0 + tx * 8;
        float2 u0 = unpack2(acc2[i][0]), u1 = unpack2(acc2[i][1]);
        float2 u2 = unpack2(acc2[i][2]), u3 = unpack2(acc2[i][3]);
        redv4(cr,     u0.x, u0.y, u1.x, u1.y);
        redv4(cr + 4, u2.x, u2.y, u3.x, u3.y);
    }
}

// WT[k*G + j] = W[j*Hs + k]
__global__ void k_transpose(int which, const float* __restrict__ W) {
    int G  = (which == 1) ? G1 : G2;
    int Hs = (which == 2) ? H2S : H1S;
    float* WT = (which == 1) ? d_whh1T : (which == 2) ? d_whh2T : d_wih2T;
    int idx = blockIdx.x * blockDim.x + threadIdx.x;
    if (idx >= G * Hs) return;
    int k = idx / G, j = idx % G;
    WT[idx] = W[(size_t)j * Hs + k];
}

// ============ fused LSTM v2 (both layers, all 12 steps) + output linear ============
// 32 blocks x 512 threads (16 warps/SM for latency hiding); block handles batches
// b0 = 2*blk, b0+1. Weight loads coalesced (8B or 4B per thread), unroll 8 for MLP.
__global__ __launch_bounds__(512) void k_lstm_fused(
    const float* __restrict__ b2v, const float* __restrict__ Wo,
    const float* __restrict__ bo, float* __restrict__ out)
{
    __shared__ __align__(16) ull hb[2][H1S];    // h1 duplicated-pair, per batch
    __shared__ __align__(16) ull hbm[H1S];      // (h1[b0,k], h1[b1,k])
    __shared__ __align__(16) ull hb2m[H2S];     // (h2[b0,k], h2[b1,k])
    __shared__ __align__(16) float gsm[2][G1];  // gate staging per batch

    int tid = threadIdx.x;
    int b0 = blockIdx.x * 2;

    if (tid < H1S) { hb[0][tid] = 0ULL; hb[1][tid] = 0ULL; hbm[tid] = 0ULL; }
    if (tid < H2S) { hb2m[tid] = 0ULL; }
    float c1 = 0.f;                       // layer1 cell for (u = tid&255, b = tid>>8)
    float c2 = 0.f;                       // layer2 cell for (u = tid&127, b = tid>>7), tid<256
    __syncthreads();

    for (int t = 0; t < SEQL; t++) {
        // ---- layer1 gates: thread handles gate pair j2 = 2*tid (coalesced 8B loads) ----
        {
            ull aA = 0, aB = 0;
            const ull* w1 = (const ull*)d_whh1T + tid;   // + k*(G1/2) per row
#pragma unroll 8
            for (int k = 0; k < H1S; k++) {
                ull w = w1[k * (G1 / 2)];
                fma2(aA, w, hb[0][k]);
                fma2(aB, w, hb[1][k]);
            }
            int j2 = tid * 2;
            float2 xa = *(const float2*)(d_xw1 + ((size_t)(t * NB + b0)) * G1 + j2);
            float2 xb = *(const float2*)(d_xw1 + ((size_t)(t * NB + b0 + 1)) * G1 + j2);
            float2 uA = unpack2(aA), uB = unpack2(aB);
            *(float2*)&gsm[0][j2] = make_float2(uA.x + xa.x, uA.y + xa.y);
            *(float2*)&gsm[1][j2] = make_float2(uB.x + xb.x, uB.y + xb.y);
        }
        __syncthreads();
        // ---- layer1 elementwise: (u, b) = (tid&255, tid>>8); PyTorch i,f,g,o ----
        {
            int u = tid & (H1S - 1), b = tid >> 8;
            float iv = sigf(gsm[b][u]);
            float fv = sigf(gsm[b][H1S + u]);
            float gv = tanhf(gsm[b][2 * H1S + u]);
            float ov = sigf(gsm[b][3 * H1S + u]);
            c1 = fv * c1 + iv * gv;
            float h = ov * tanhf(c1);
            hb[b][u] = pack2(h, h);
            ((float*)&hbm[u])[b] = h;
        }
        __syncthreads();
        // ---- layer2 gates: thread handles gate j = tid (coalesced 4B loads) ----
        {
            int j = tid;
            ull a = 0;
            const float* w2 = d_wih2T + j;
#pragma unroll 8
            for (int k = 0; k < H1S; k++) {
                float w = w2[k * G2];
                fma2(a, pack2(w, w), hbm[k]);
            }
            const float* w3 = d_whh2T + j;
#pragma unroll 8
            for (int k = 0; k < H2S; k++) {
                float w = w3[k * G2];
                fma2(a, pack2(w, w), hb2m[k]);
            }
            float bb = __ldg(b2v + j);
            float2 u = unpack2(a);
            gsm[0][j] = u.x + bb;
            gsm[1][j] = u.y + bb;
        }
        __syncthreads();
        // ---- layer2 elementwise: tid < 256; (u, b) = (tid&127, tid>>7) ----
        if (tid < 2 * H2S) {
            int u = tid & (H2S - 1), b = tid >> 7;
            float iv = sigf(gsm[b][u]);
            float fv = sigf(gsm[b][H2S + u]);
            float gv = tanhf(gsm[b][2 * H2S + u]);
            float ov = sigf(gsm[b][3 * H2S + u]);
            c2 = fv * c2 + iv * gv;
            float h = ov * tanhf(c2);
            ((float*)&hb2m[u])[b] = h;
        }
        __syncthreads();
    }

    // ---- output linear: out[b, jj] = Wo[jj,:]·h2[b] + bo[jj] ----
    for (int jj = tid; jj < NN * 2; jj += 512) {
        const float* wr = Wo + (size_t)jj * H2S;
        ull acc = 0;
#pragma unroll 8
        for (int k = 0; k < H2S; k++) {
            float w = __ldg(wr + k);
            fma2(acc, pack2(w, w), hb2m[k]);
        }
        float2 u = unpack2(acc);
        float bv = __ldg(bo + jj);
        out[(size_t)b0 * (NN * 2) + jj]       = u.x + bv;
        out[(size_t)(b0 + 1) * (NN * 2) + jj] = u.y + bv;
    }
}

// ---------------- launch ----------------
extern "C" void kernel_launch(void* const* d_in, const int* in_sizes, int n_in,
                              void* d_out, int out_size) {
    const float* x     = (const float*)d_in[0];
    const int*   ei    = (const int*)d_in[1];     // int32 (JAX x64 disabled)
    const float* Wg    = (const float*)d_in[2];
    const float* att_s = (const float*)d_in[3];
    const float* att_d = (const float*)d_in[4];
    const float* gbias = (const float*)d_in[5];
    const float* Wih1  = (const float*)d_in[6];
    const float* Whh1  = (const float*)d_in[7];
    const float* b1    = (const float*)d_in[8];
    const float* Wih2  = (const float*)d_in[9];
    const float* Whh2  = (const float*)d_in[10];
    const float* b2    = (const float*)d_in[11];
    const float* Wo    = (const float*)d_in[12];
    const float* bo    = (const float*)d_in[13];
    float* out = (float*)d_out;

    int E = in_sizes[1] / 2;
    if (E > EMAX) E = EMAX;
    int etot = E + NTOT;

    // Order matters: ncu captures the 4th launch -> put k_passA there this round.
    k_gemm_h<<<(NTOT * 48 + 255) / 256, 256>>>(x, Wg);            // 1
    k_init<<<(NTOT * 48 + 255) / 256, 256>>>();                   // 2
    k_attn<<<(NTOT * 2 + 255) / 256, 256>>>(att_s, att_d);        // 3
    k_passA<<<(etot * 2 + 255) / 256, 256>>>(ei, E);              // 4  <- profiled
    k_passB<<<(etot * 2 + 255) / 256, 256>>>(ei, E);              // 5
    k_passC<<<(etot * 12 + 255) / 256, 256>>>(ei, E);             // 6

    k_wsum<<<G1, 128>>>(Wih1);
    k_biasinit<<<(TBR * G1 + 255) / 256, 256>>>(b1, gbias);
    k_transpose<<<(H1S * G1 + 255) / 256, 256>>>(1, Whh1);
    k_transpose<<<(H2S * G2 + 255) / 256, 256>>>(2, Whh2);
    k_transpose<<<(H1S * G2 + 255) / 256, 256>>>(3, Wih2);

    k_sgemm1<<<dim3(G1 / 64, SEQL, SPLITK), 128>>>(Wih1);
    k_lstm_fused<<<NB / 2, 512>>>(b2, Wo, bo, out);
}

// round 12
// speedup vs baseline: 1.2313x; 1.1231x over previous
#include <cuda_runtime.h>
#include <math.h>

// ---------------- problem constants ----------------
#define NB    64        // batch
#define NN    1000      // nodes per sample
#define NTOT  64000     // NB*NN
#define SEQL  12
#define D1    4000      // NN*FEAT
#define H1S   256
#define H2S   128
#define G1    1024      // 4*H1S
#define G2    512       // 4*H2S
#define TBR   768       // SEQL*NB
#define EMAX  1024000
#define ETOTMAX (EMAX + NTOT)
#define SPLITK 10       // K=4000 -> klen=400, multiple of 16

typedef unsigned long long ull;

// ---------------- scratch (device globals; no allocation allowed) ----------------
__device__ __align__(256) float d_h[NTOT * 96];        // GAT hidden, [n][head][c]
__device__ __align__(256) float d_asrc[NTOT * 2];
__device__ __align__(256) float d_adst[NTOT * 2];
__device__ __align__(256) float d_m[NTOT * 2];         // segment max
__device__ __align__(256) float d_den[NTOT * 2];       // segment sum
__device__ __align__(256) float d_w[ETOTMAX * 2];      // leaky value -> softmax numerator
__device__ __align__(256) float d_g[NTOT * 48];        // GAT output (head-mean, no bias)
__device__ __align__(256) float d_xw1[TBR * G1];       // LSTM1 input projection
__device__ __align__(256) float d_whh1T[H1S * G1];
__device__ __align__(256) float d_whh2T[H2S * G2];
__device__ __align__(256) float d_wih2T[H1S * G2];
__device__ __align__(256) float d_ws[G1 * 4];          // col-sums of W_ih1 per (j, f)
// LSTM state, layout [unit][batch] (u*64 + b)
__device__ __align__(256) float d_h1g[H1S * NB];
__device__ __align__(256) float d_c1g[H1S * NB];
__device__ __align__(256) float d_h2g[H2S * NB];
__device__ __align__(256) float d_c2g[H2S * NB];

// ---------------- helpers ----------------
__device__ __forceinline__ float sigf(float x) { return 1.f / (1.f + expf(-x)); }

__device__ __forceinline__ void atomicMaxF(float* addr, float v) {
    if (v >= 0.f) atomicMax((int*)addr, __float_as_int(v));
    else          atomicMin((unsigned int*)addr, __float_as_uint(v));
}

// packed f32x2 FMA (FFMA2)
__device__ __forceinline__ void fma2(ull& acc, ull a, ull b) {
    asm("fma.rn.f32x2 %0, %1, %2, %0;" : "+l"(acc) : "l"(a), "l"(b));
}
__device__ __forceinline__ ull pack2(float x, float y) {
    ull r; asm("mov.b64 %0, {%1, %2};" : "=l"(r) : "f"(x), "f"(y)); return r;
}
__device__ __forceinline__ float2 unpack2(ull v) {
    float2 r; asm("mov.b64 {%0, %1}, %2;" : "=f"(r.x), "=f"(r.y) : "l"(v)); return r;
}
__device__ __forceinline__ void redv4(float* dst, float a, float b, float c, float d) {
    asm volatile("red.global.add.v4.f32 [%0], {%1, %2, %3, %4};"
                 :: "l"(dst), "f"(a), "f"(b), "f"(c), "f"(d) : "memory");
}

// ---------------- kernels ----------------
__global__ void k_init() {
    int idx = blockIdx.x * blockDim.x + threadIdx.x;
    if (idx < NTOT * 48) d_g[idx] = 0.f;
    if (idx < NTOT * 2) { d_m[idx] = __int_as_float(0xff800000); d_den[idx] = 0.f; }
    if (idx < H1S * NB) { d_h1g[idx] = 0.f; d_c1g[idx] = 0.f; }
    if (idx < H2S * NB) { d_h2g[idx] = 0.f; d_c2g[idx] = 0.f; }
}

// ws[j, f] = sum_n W_ih1[j, 4n+f] ; one block per j, 128 threads
__global__ void k_wsum(const float* __restrict__ W) {
    __shared__ float part[128];
    int j = blockIdx.x;
    const float* wr = W + (size_t)j * D1;
    float acc = 0.f;
    for (int e = threadIdx.x; e < D1; e += 128) acc += __ldg(wr + e);   // f = e&3 fixed per thread
    part[threadIdx.x] = acc;
    __syncthreads();
    if (threadIdx.x < 4) {
        float s = 0.f;
        for (int i = threadIdx.x; i < 128; i += 4) s += part[i];
        d_ws[j * 4 + threadIdx.x] = s;
    }
}

// d_xw1[(t*NB+b)*G1 + j] = b1[j] + sum_f gbias[4t+f] * ws[j,f]
__global__ void k_biasinit(const float* __restrict__ b1, const float* __restrict__ gbias) {
    int idx = blockIdx.x * blockDim.x + threadIdx.x;
    if (idx >= TBR * G1) return;
    int j = idx & (G1 - 1);
    int t = idx / (G1 * NB);
    float v = __ldg(b1 + j);
#pragma unroll
    for (int f = 0; f < 4; f++) v = fmaf(__ldg(gbias + t * 4 + f), d_ws[j * 4 + f], v);
    d_xw1[idx] = v;
}

// h[n, j2:j2+2] = sum_k x[n,k] * Wg[k, j2:j2+2]   (f32x2)
__global__ void k_gemm_h(const float* __restrict__ x, const float* __restrict__ Wg) {
    __shared__ __align__(16) float ws[48 * 96];
    for (int i = threadIdx.x; i < 48 * 96; i += blockDim.x) ws[i] = Wg[i];
    __syncthreads();
    int idx = blockIdx.x * blockDim.x + threadIdx.x;
    if (idx >= NTOT * 48) return;
    int n = idx / 48, j2 = (idx % 48) * 2;
    const float* xr = x + (size_t)n * 48;
    ull acc = 0;
#pragma unroll
    for (int k = 0; k < 48; k++) {
        float xv = __ldg(xr + k);
        fma2(acc, pack2(xv, xv), *(const ull*)(ws + k * 96 + j2));
    }
    float2 u = unpack2(acc);
    *(float2*)(d_h + (size_t)n * 96 + j2) = u;
}

__global__ void k_attn(const float* __restrict__ att_s, const float* __restrict__ att_d) {
    int idx = blockIdx.x * blockDim.x + threadIdx.x;
    if (idx >= NTOT * 2) return;
    int n = idx >> 1, hd = idx & 1;
    const float* hr = d_h + (size_t)n * 96 + hd * 48;
    float s1 = 0.f, s2 = 0.f;
#pragma unroll
    for (int c = 0; c < 48; c++) {
        float hv = hr[c];
        s1 = fmaf(hv, __ldg(att_s + hd * 48 + c), s1);
        s2 = fmaf(hv, __ldg(att_d + hd * 48 + c), s2);
    }
    d_asrc[idx] = s1;
    d_adst[idx] = s2;
}

// edge_index arrives as int32 (JAX x64 disabled)
__device__ __forceinline__ void edge_sd(const int* __restrict__ ei, int E, int e,
                                        int& s, int& d) {
    if (e < E) { s = ei[e]; d = ei[E + e]; }
    else       { s = e - E; d = s; }
}

// compute leaky value v, store to d_w, atomicMax into d_m
__global__ void k_passA(const int* __restrict__ ei, int E) {
    int idx = blockIdx.x * blockDim.x + threadIdx.x;
    int etot = E + NTOT;
    if (idx >= etot * 2) return;
    int e = idx >> 1, hd = idx & 1;
    int s, d; edge_sd(ei, E, e, s, d);
    float v = d_asrc[s * 2 + hd] + d_adst[d * 2 + hd];
    v = v > 0.f ? v : 0.2f * v;
    d_w[idx] = v;
    atomicMaxF(&d_m[d * 2 + hd], v);
}

// w = exp(v - m[d]); store; accumulate den
__global__ void k_passB(const int* __restrict__ ei, int E) {
    int idx = blockIdx.x * blockDim.x + threadIdx.x;
    int etot = E + NTOT;
    if (idx >= etot * 2) return;
    int e = idx >> 1, hd = idx & 1;
    int d = (e < E) ? ei[E + e] : (e - E);
    float w = expf(d_w[idx] - d_m[d * 2 + hd]);
    d_w[idx] = w;
    atomicAdd(&d_den[d * 2 + hd], w);
}

// g[dst, q*4:+4] += a0*h[src,0,...] + a1*h[src,1,...]
// normalization (0.5/(den+eps)) inline (fast division; den >= 1)
__global__ void k_passC(const int* __restrict__ ei, int E) {
    int idx = blockIdx.x * blockDim.x + threadIdx.x;
    int etot = E + NTOT;
    if (idx >= etot * 12) return;
    int e = idx / 12, q = idx - e * 12;
    int s, d; edge_sd(ei, E, e, s, d);
    float2 a  = *(const float2*)(d_w + (size_t)e * 2);
    float2 dn = *(const float2*)(d_den + (size_t)d * 2);
    float a0 = a.x * __fdividef(0.5f, dn.x + 1e-16f);
    float a1 = a.y * __fdividef(0.5f, dn.y + 1e-16f);
    const float4 h0 = *(const float4*)(d_h + (size_t)s * 96 + q * 4);
    const float4 h1 = *(const float4*)(d_h + (size_t)s * 96 + 48 + q * 4);
    float vx = fmaf(a0, h0.x, a1 * h1.x);
    float vy = fmaf(a0, h0.y, a1 * h1.y);
    float vz = fmaf(a0, h0.z, a1 * h1.z);
    float vw = fmaf(a0, h0.w, a1 * h1.w);
    redv4(d_g + (size_t)d * 48 + q * 4, vx, vy, vz, vw);
}

// NT SGEMM, A read directly from d_g (reshape folded into indexing).
// C = d_xw1 (pre-init'd with bias+WS), split-K via blockIdx.z, red-v4 epilogue.
__global__ void k_sgemm1(const float* __restrict__ B) {
    const int K = D1, N = G1;
    __shared__ __align__(16) float As[16][64];
    __shared__ __align__(16) float Bs[16][64];
    int t = threadIdx.x;
    int ty = t >> 3;              // 0..15
    int tx = t & 7;               // 0..7
    int tq = blockIdx.y * 4;      // time index * FEAT
    int m0 = blockIdx.y * 64;
    int n0 = blockIdx.x * 64;
    int klen = K / SPLITK;        // 400
    int kbeg = blockIdx.z * klen;

    ull acc2[4][4];
#pragma unroll
    for (int i = 0; i < 4; i++)
#pragma unroll
        for (int j = 0; j < 4; j++) acc2[i][j] = 0ULL;

    for (int k0 = kbeg; k0 < kbeg + klen; k0 += 16) {
#pragma unroll
        for (int l = 0; l < 2; l++) {
            int lin = t + l * 128;        // 0..255
            int mm = lin & 63;
            int kk4 = lin >> 6;           // 0..3
            float4 av = *(const float4*)(d_g + ((size_t)mm * NN + (k0 >> 2) + kk4) * 48 + tq);
            As[kk4 * 4 + 0][mm] = av.x; As[kk4 * 4 + 1][mm] = av.y;
            As[kk4 * 4 + 2][mm] = av.z; As[kk4 * 4 + 3][mm] = av.w;
            float4 bv = *(const float4*)(B + (size_t)(n0 + mm) * K + k0 + kk4 * 4);
            Bs[kk4 * 4 + 0][mm] = bv.x; Bs[kk4 * 4 + 1][mm] = bv.y;
            Bs[kk4 * 4 + 2][mm] = bv.z; Bs[kk4 * 4 + 3][mm] = bv.w;
        }
        __syncthreads();
#pragma unroll
        for (int kk = 0; kk < 16; kk++) {
            float4 a = *(const float4*)&As[kk][ty * 4];
            ull ad0 = pack2(a.x, a.x), ad1 = pack2(a.y, a.y);
            ull ad2 = pack2(a.z, a.z), ad3 = pack2(a.w, a.w);
            const ull* bp = (const ull*)&Bs[kk][tx * 8];
            ull b0 = bp[0], b1 = bp[1], b2 = bp[2], b3 = bp[3];
            fma2(acc2[0][0], ad0, b0); fma2(acc2[0][1], ad0, b1);
            fma2(acc2[0][2], ad0, b2); fma2(acc2[0][3], ad0, b3);
            fma2(acc2[1][0], ad1, b0); fma2(acc2[1][1], ad1, b1);
            fma2(acc2[1][2], ad1, b2); fma2(acc2[1][3], ad1, b3);
            fma2(acc2[2][0], ad2, b0); fma2(acc2[2][1], ad2, b1);
            fma2(acc2[2][2], ad2, b2); fma2(acc2[2][3], ad2, b3);
            fma2(acc2[3][0], ad3, b0); fma2(acc2[3][1], ad3, b1);
            fma2(acc2[3][2], ad3, b2); fma2(acc2[3][3], ad3, b3);
        }
        __syncthreads();
    }
#pragma unroll
    for (int i = 0; i < 4; i++) {
        int m = m0 + ty * 4 + i;
        float* cr = d_xw1 + (size_t)m * N + n0 + tx * 8;
        float2 u0 = unpack2(acc2[i][0]), u1 = unpack2(acc2[i][1]);
        float2 u2 = unpack2(acc2[i][2]), u3 = unpack2(acc2[i][3]);
        redv4(cr,     u0.x, u0.y, u1.x, u1.y);
        redv4(cr + 4, u2.x, u2.y, u3.x, u3.y);
    }
}

// WT[k*G + j] = W[j*Hs + k]
__global__ void k_transpose(int which, const float* __restrict__ W) {
    int G  = (which == 1) ? G1 : G2;
    int Hs = (which == 2) ? H2S : H1S;
    float* WT = (which == 1) ? d_whh1T : (which == 2) ? d_whh2T : d_wih2T;
    int idx = blockIdx.x * blockDim.x + threadIdx.x;
    if (idx >= G * Hs) return;
    int k = idx / G, j = idx % G;
    WT[idx] = W[(size_t)j * Hs + k];
}

// ============ per-step LSTM kernels: gates + elementwise fused ============
// Layer 1 step: grid (16 u-blocks, 4 b-blocks), 256 threads.
// Block owns units [u0, u0+16) (all 4 gates -> elem is block-local) x 16 batches.
// Thread (jj = tid&63, bq = tid>>6): gate j = (jj>>4)*H1S + u0 + (jj&15), batches bq*4..+3.
__global__ __launch_bounds__(256) void k_step1(int t) {
    __shared__ __align__(16) float hs[H1S][16];
    __shared__ float gsm[64][17];
    int tid = threadIdx.x;
    int u0 = blockIdx.x * 16;
    int b0 = blockIdx.y * 16;
    for (int i = tid; i < H1S * 16; i += 256)
        hs[i >> 4][i & 15] = d_h1g[(i >> 4) * NB + b0 + (i & 15)];
    __syncthreads();

    int jj = tid & 63, bq = tid >> 6;
    int j = (jj >> 4) * H1S + u0 + (jj & 15);
    ull a01 = 0, a23 = 0;
    const float* wp = d_whh1T + j;
#pragma unroll 8
    for (int k = 0; k < H1S; k++) {
        float w = wp[k * G1];
        ull wd = pack2(w, w);
        const ull* hp = (const ull*)&hs[k][bq * 4];
        fma2(a01, wd, hp[0]);
        fma2(a23, wd, hp[1]);
    }
    {
        float2 u01 = unpack2(a01), u23 = unpack2(a23);
        float gv4[4] = {u01.x, u01.y, u23.x, u23.y};
#pragma unroll
        for (int i = 0; i < 4; i++) {
            int b = b0 + bq * 4 + i;
            gsm[jj][bq * 4 + i] = gv4[i] + d_xw1[((size_t)(t * NB + b)) * G1 + j];
        }
    }
    __syncthreads();
    {
        int bl = tid & 15, ul = tid >> 4;    // 16 units x 16 batches
        float iv = sigf(gsm[ul][bl]);
        float fv = sigf(gsm[16 + ul][bl]);
        float gv = tanhf(gsm[32 + ul][bl]);
        float ov = sigf(gsm[48 + ul][bl]);
        int ci = (u0 + ul) * NB + b0 + bl;
        float c = fv * d_c1g[ci] + iv * gv;
        d_c1g[ci] = c;
        d_h1g[ci] = ov * tanhf(c);
    }
}

// Layer 2 step: grid (8 u-blocks, 4 b-blocks), 256 threads. Input dot over h1 (256)
// plus recurrent dot over h2 (128); bias b2.
__global__ __launch_bounds__(256) void k_step2(int t, const float* __restrict__ b2v) {
    __shared__ __align__(16) float h1s[H1S][16];
    __shared__ __align__(16) float h2s[H2S][16];
    __shared__ float gsm[64][17];
    int tid = threadIdx.x;
    int u0 = blockIdx.x * 16;
    int b0 = blockIdx.y * 16;
    for (int i = tid; i < H1S * 16; i += 256)
        h1s[i >> 4][i & 15] = d_h1g[(i >> 4) * NB + b0 + (i & 15)];
    for (int i = tid; i < H2S * 16; i += 256)
        h2s[i >> 4][i & 15] = d_h2g[(i >> 4) * NB + b0 + (i & 15)];
    __syncthreads();

    int jj = tid & 63, bq = tid >> 6;
    int j = (jj >> 4) * H2S + u0 + (jj & 15);
    ull a01 = 0, a23 = 0;
    const float* wp = d_wih2T + j;
#pragma unroll 8
    for (int k = 0; k < H1S; k++) {
        float w = wp[k * G2];
        ull wd = pack2(w, w);
        const ull* hp = (const ull*)&h1s[k][bq * 4];
        fma2(a01, wd, hp[0]);
        fma2(a23, wd, hp[1]);
    }
    const float* wq = d_whh2T + j;
#pragma unroll 8
    for (int k = 0; k < H2S; k++) {
        float w = wq[k * G2];
        ull wd = pack2(w, w);
        const ull* hp = (const ull*)&h2s[k][bq * 4];
        fma2(a01, wd, hp[0]);
        fma2(a23, wd, hp[1]);
    }
    {
        float bb = __ldg(b2v + j);
        float2 u01 = unpack2(a01), u23 = unpack2(a23);
        gsm[jj][bq * 4 + 0] = u01.x + bb;
        gsm[jj][bq * 4 + 1] = u01.y + bb;
        gsm[jj][bq * 4 + 2] = u23.x + bb;
        gsm[jj][bq * 4 + 3] = u23.y + bb;
    }
    __syncthreads();
    {
        int bl = tid & 15, ul = tid >> 4;
        float iv = sigf(gsm[ul][bl]);
        float fv = sigf(gsm[16 + ul][bl]);
        float gv = tanhf(gsm[32 + ul][bl]);
        float ov = sigf(gsm[48 + ul][bl]);
        int ci = (u0 + ul) * NB + b0 + bl;
        float c = fv * d_c2g[ci] + iv * gv;
        d_c2g[ci] = c;
        d_h2g[ci] = ov * tanhf(c);
    }
}

// out[b*2000 + j] = sum_k h2[k][b] * W_out[j,k] + b_out[j]
__global__ void k_out(const float* __restrict__ Wo, const float* __restrict__ bo,
                      float* __restrict__ out) {
    __shared__ __align__(16) float hr[H2S];
    int b = blockIdx.y;
    if (threadIdx.x < H2S) hr[threadIdx.x] = d_h2g[threadIdx.x * NB + b];
    __syncthreads();
    int j = blockIdx.x * blockDim.x + threadIdx.x;
    if (j >= NN * 2) return;
    const ull* wp = (const ull*)(Wo + (size_t)j * H2S);
    const ull* hp = (const ull*)hr;
    ull accA = 0, accB = 0;
#pragma unroll 8
    for (int k = 0; k < H2S / 2; k += 2) {
        fma2(accA, hp[k], wp[k]);
        fma2(accB, hp[k + 1], wp[k + 1]);
    }
    float2 uA = unpack2(accA), uB = unpack2(accB);
    out[(size_t)b * (NN * 2) + j] = uA.x + uA.y + uB.x + uB.y + __ldg(bo + j);
}

// ---------------- launch ----------------
extern "C" void kernel_launch(void* const* d_in, const int* in_sizes, int n_in,
                              void* d_out, int out_size) {
    const float* x     = (const float*)d_in[0];
    const int*   ei    = (const int*)d_in[1];     // int32 (JAX x64 disabled)
    const float* Wg    = (const float*)d_in[2];
    const float* att_s = (const float*)d_in[3];
    const float* att_d = (const float*)d_in[4];
    const float* gbias = (const float*)d_in[5];
    const float* Wih1  = (const float*)d_in[6];
    const float* Whh1  = (const float*)d_in[7];
    const float* b1    = (const float*)d_in[8];
    const float* Wih2  = (const float*)d_in[9];
    const float* Whh2  = (const float*)d_in[10];
    const float* b2    = (const float*)d_in[11];
    const float* Wo    = (const float*)d_in[12];
    const float* bo    = (const float*)d_in[13];
    float* out = (float*)d_out;

    int E = in_sizes[1] / 2;
    if (E > EMAX) E = EMAX;
    int etot = E + NTOT;

    // ncu captures launch #4 -> k_gemm_h profiled this round.
    k_wsum<<<G1, 128>>>(Wih1);                                     // 1
    k_biasinit<<<(TBR * G1 + 255) / 256, 256>>>(b1, gbias);        // 2
    k_init<<<(NTOT * 48 + 255) / 256, 256>>>();                    // 3
    k_gemm_h<<<(NTOT * 48 + 255) / 256, 256>>>(x, Wg);             // 4  <- profiled
    k_attn<<<(NTOT * 2 + 255) / 256, 256>>>(att_s, att_d);         // 5
    k_passA<<<(etot * 2 + 255) / 256, 256>>>(ei, E);               // 6
    k_passB<<<(etot * 2 + 255) / 256, 256>>>(ei, E);               // 7
    k_passC<<<(etot * 12 + 255) / 256, 256>>>(ei, E);              // 8

    k_transpose<<<(H1S * G1 + 255) / 256, 256>>>(1, Whh1);
    k_transpose<<<(H2S * G2 + 255) / 256, 256>>>(2, Whh2);
    k_transpose<<<(H1S * G2 + 255) / 256, 256>>>(3, Wih2);

    k_sgemm1<<<dim3(G1 / 64, SEQL, SPLITK), 128>>>(Wih1);

    for (int t = 0; t < SEQL; t++) {
        k_step1<<<dim3(16, 4), 256>>>(t);
        k_step2<<<dim3(8, 4), 256>>>(t, b2);
    }
    k_out<<<dim3((NN * 2 + 255) / 256, NB), 256>>>(Wo, bo, out);
}

// round 13
// speedup vs baseline: 1.3240x; 1.0753x over previous
#include <cuda_runtime.h>
#include <math.h>

// ---------------- problem constants ----------------
#define NB    64        // batch
#define NN    1000      // nodes per sample
#define NTOT  64000     // NB*NN
#define SEQL  12
#define D1    4000      // NN*FEAT
#define H1S   256
#define H2S   128
#define G1    1024      // 4*H1S
#define G2    512       // 4*H2S
#define TBR   768       // SEQL*NB
#define EMAX  1024000
#define ETOTMAX (EMAX + NTOT)
#define SPLITK 10       // K=4000 -> klen=400, multiple of 16

typedef unsigned long long ull;

// ---------------- scratch (device globals; no allocation allowed) ----------------
__device__ __align__(256) float d_h[NTOT * 96];        // GAT hidden, [n][head][c]
__device__ __align__(256) float d_asrc[NTOT * 2];
__device__ __align__(256) float d_adst[NTOT * 2];
__device__ __align__(256) float d_den[NTOT * 2];       // segment sum of exp
__device__ __align__(256) float d_w[ETOTMAX * 2];      // softmax numerator exp(v)
__device__ __align__(256) float d_g[NTOT * 48];        // GAT output (head-mean, no bias)
__device__ __align__(256) float d_xw1[TBR * G1];       // LSTM1 input projection
__device__ __align__(256) float d_whh1T[H1S * G1];
__device__ __align__(256) float d_whh2T[H2S * G2];
__device__ __align__(256) float d_wih2T[H1S * G2];
__device__ __align__(256) float d_ws[G1 * 4];          // col-sums of W_ih1 per (j, f)
// LSTM state, layout [unit][batch] (u*64 + b)
__device__ __align__(256) float d_h1g[H1S * NB];
__device__ __align__(256) float d_c1g[H1S * NB];
__device__ __align__(256) float d_h2g[H2S * NB];
__device__ __align__(256) float d_c2g[H2S * NB];

// ---------------- helpers ----------------
__device__ __forceinline__ float sigf(float x) { return 1.f / (1.f + expf(-x)); }

// packed f32x2 FMA (FFMA2)
__device__ __forceinline__ void fma2(ull& acc, ull a, ull b) {
    asm("fma.rn.f32x2 %0, %1, %2, %0;" : "+l"(acc) : "l"(a), "l"(b));
}
__device__ __forceinline__ ull pack2(float x, float y) {
    ull r; asm("mov.b64 %0, {%1, %2};" : "=l"(r) : "f"(x), "f"(y)); return r;
}
__device__ __forceinline__ float2 unpack2(ull v) {
    float2 r; asm("mov.b64 {%0, %1}, %2;" : "=f"(r.x), "=f"(r.y) : "l"(v)); return r;
}
__device__ __forceinline__ void redv4(float* dst, float a, float b, float c, float d) {
    asm volatile("red.global.add.v4.f32 [%0], {%1, %2, %3, %4};"
                 :: "l"(dst), "f"(a), "f"(b), "f"(c), "f"(d) : "memory");
}

// ---------------- kernels ----------------
__global__ void k_init() {
    int idx = blockIdx.x * blockDim.x + threadIdx.x;
    if (idx < NTOT * 48) d_g[idx] = 0.f;
    if (idx < NTOT * 2) d_den[idx] = 0.f;
    if (idx < H1S * NB) { d_h1g[idx] = 0.f; d_c1g[idx] = 0.f; }
    if (idx < H2S * NB) { d_h2g[idx] = 0.f; d_c2g[idx] = 0.f; }
}

// ws[j, f] = sum_n W_ih1[j, 4n+f] ; one block per j, 128 threads
__global__ void k_wsum(const float* __restrict__ W) {
    __shared__ float part[128];
    int j = blockIdx.x;
    const float* wr = W + (size_t)j * D1;
    float acc = 0.f;
    for (int e = threadIdx.x; e < D1; e += 128) acc += __ldg(wr + e);   // f = e&3 fixed per thread
    part[threadIdx.x] = acc;
    __syncthreads();
    if (threadIdx.x < 4) {
        float s = 0.f;
        for (int i = threadIdx.x; i < 128; i += 4) s += part[i];
        d_ws[j * 4 + threadIdx.x] = s;
    }
}

// d_xw1[(t*NB+b)*G1 + j] = b1[j] + sum_f gbias[4t+f] * ws[j,f]
__global__ void k_biasinit(const float* __restrict__ b1, const float* __restrict__ gbias) {
    int idx = blockIdx.x * blockDim.x + threadIdx.x;
    if (idx >= TBR * G1) return;
    int j = idx & (G1 - 1);
    int t = idx / (G1 * NB);
    float v = __ldg(b1 + j);
#pragma unroll
    for (int f = 0; f < 4; f++) v = fmaf(__ldg(gbias + t * 4 + f), d_ws[j * 4 + f], v);
    d_xw1[idx] = v;
}

// ===== GAT projection (tiled GEMM) + attention coefficients, fused =====
// Block: 64 nodes, all 96 output cols, K=48. 256 threads.
// Thread (tx = tid&15 -> 6 cols, ty = tid>>4 -> 4 nodes): 4x3 f32x2 microtile.
// Epilogue computes a_src/a_dst via per-thread partial dots + smem reduction.
__global__ __launch_bounds__(256) void k_gemm_attn(
    const float* __restrict__ x, const float* __restrict__ Wg,
    const float* __restrict__ att_s, const float* __restrict__ att_d)
{
    __shared__ __align__(16) float xs[48][68];   // [k][node], padded stride
    __shared__ __align__(16) float ws[48][96];   // [k][col]
    __shared__ float als[96], ald[96];
    __shared__ float red1[64][17], red2[64][17];
    int tid = threadIdx.x;
    int n0 = blockIdx.x * 64;

    for (int i = tid; i < 48 * 96 / 4; i += 256) {
        float4 v = ((const float4*)Wg)[i];
        int k = i / 24, j = (i % 24) * 4;
        *(float4*)&ws[k][j] = v;
    }
    if (tid < 96) { als[tid] = __ldg(att_s + tid); ald[tid] = __ldg(att_d + tid); }
    for (int i = tid; i < 64 * 12; i += 256) {
        int node = i / 12, kq = i % 12;
        float4 v = ((const float4*)(x + (size_t)(n0 + node) * 48))[kq];
        xs[kq * 4 + 0][node] = v.x; xs[kq * 4 + 1][node] = v.y;
        xs[kq * 4 + 2][node] = v.z; xs[kq * 4 + 3][node] = v.w;
    }
    __syncthreads();

    int tx = tid & 15, ty = tid >> 4;
    int c0 = tx * 6;
    ull acc[4][3];
#pragma unroll
    for (int i = 0; i < 4; i++)
#pragma unroll
        for (int p = 0; p < 3; p++) acc[i][p] = 0ULL;

#pragma unroll 4
    for (int k = 0; k < 48; k++) {
        float4 a = *(const float4*)&xs[k][ty * 4];
        const ull* bp = (const ull*)&ws[k][c0];
        ull b0 = bp[0], b1 = bp[1], b2 = bp[2];
        ull a0 = pack2(a.x, a.x), a1 = pack2(a.y, a.y);
        ull a2 = pack2(a.z, a.z), a3 = pack2(a.w, a.w);
        fma2(acc[0][0], a0, b0); fma2(acc[0][1], a0, b1); fma2(acc[0][2], a0, b2);
        fma2(acc[1][0], a1, b0); fma2(acc[1][1], a1, b1); fma2(acc[1][2], a1, b2);
        fma2(acc[2][0], a2, b0); fma2(acc[2][1], a2, b1); fma2(acc[2][2], a2, b2);
        fma2(acc[3][0], a3, b0); fma2(acc[3][1], a3, b1); fma2(acc[3][2], a3, b2);
    }

    // store h + partial attention dots
#pragma unroll
    for (int i = 0; i < 4; i++) {
        int node = ty * 4 + i;
        float s1 = 0.f, s2 = 0.f;
#pragma unroll
        for (int p = 0; p < 3; p++) {
            float2 hv = unpack2(acc[i][p]);
            int c = c0 + p * 2;
            s1 = fmaf(hv.x, als[c], fmaf(hv.y, als[c + 1], s1));
            s2 = fmaf(hv.x, ald[c], fmaf(hv.y, ald[c + 1], s2));
            *(float2*)(d_h + (size_t)(n0 + node) * 96 + c) = hv;
        }
        red1[node][tx] = s1;
        red2[node][tx] = s2;
    }
    __syncthreads();
    if (tid < 128) {
        int node = tid & 63, head = tid >> 6;
        float s1 = 0.f, s2 = 0.f;
#pragma unroll
        for (int q = 0; q < 8; q++) {
            s1 += red1[node][head * 8 + q];
            s2 += red2[node][head * 8 + q];
        }
        d_asrc[(size_t)(n0 + node) * 2 + head] = s1;
        d_adst[(size_t)(n0 + node) * 2 + head] = s2;
    }
}

// edge_index arrives as int32 (JAX x64 disabled)
__device__ __forceinline__ void edge_sd(const int* __restrict__ ei, int E, int e,
                                        int& s, int& d) {
    if (e < E) { s = ei[e]; d = ei[E + e]; }
    else       { s = e - E; d = s; }
}

// Softmax WITHOUT max-subtraction (|v| <~ 1 here; exp(v)/sum(exp(v)) is exact math-equal).
// w = exp(leaky(asrc[s]+adst[d])); accumulate den.
__global__ void k_passAB(const int* __restrict__ ei, int E) {
    int idx = blockIdx.x * blockDim.x + threadIdx.x;
    int etot = E + NTOT;
    if (idx >= etot * 2) return;
    int e = idx >> 1, hd = idx & 1;
    int s, d; edge_sd(ei, E, e, s, d);
    float v = d_asrc[s * 2 + hd] + d_adst[d * 2 + hd];
    v = v > 0.f ? v : 0.2f * v;
    float w = expf(v);
    d_w[idx] = w;
    atomicAdd(&d_den[d * 2 + hd], w);
}

// g[dst, q*4:+4] += a0*h[src,0,...] + a1*h[src,1,...]
// normalization (0.5/(den+eps)) inline (fast division; den > 0)
__global__ void k_passC(const int* __restrict__ ei, int E) {
    int idx = blockIdx.x * blockDim.x + threadIdx.x;
    int etot = E + NTOT;
    if (idx >= etot * 12) return;
    int e = idx / 12, q = idx - e * 12;
    int s, d; edge_sd(ei, E, e, s, d);
    float2 a  = *(const float2*)(d_w + (size_t)e * 2);
    float2 dn = *(const float2*)(d_den + (size_t)d * 2);
    float a0 = a.x * __fdividef(0.5f, dn.x + 1e-16f);
    float a1 = a.y * __fdividef(0.5f, dn.y + 1e-16f);
    const float4 h0 = *(const float4*)(d_h + (size_t)s * 96 + q * 4);
    const float4 h1 = *(const float4*)(d_h + (size_t)s * 96 + 48 + q * 4);
    float vx = fmaf(a0, h0.x, a1 * h1.x);
    float vy = fmaf(a0, h0.y, a1 * h1.y);
    float vz = fmaf(a0, h0.z, a1 * h1.z);
    float vw = fmaf(a0, h0.w, a1 * h1.w);
    redv4(d_g + (size_t)d * 48 + q * 4, vx, vy, vz, vw);
}

// NT SGEMM, A read directly from d_g (reshape folded into indexing).
// C = d_xw1 (pre-init'd with bias+WS), split-K via blockIdx.z, red-v4 epilogue.
__global__ void k_sgemm1(const float* __restrict__ B) {
    const int K = D1, N = G1;
    __shared__ __align__(16) float As[16][64];
    __shared__ __align__(16) float Bs[16][64];
    int t = threadIdx.x;
    int ty = t >> 3;              // 0..15
    int tx = t & 7;               // 0..7
    int tq = blockIdx.y * 4;      // time index * FEAT
    int m0 = blockIdx.y * 64;
    int n0 = blockIdx.x * 64;
    int klen = K / SPLITK;        // 400
    int kbeg = blockIdx.z * klen;

    ull acc2[4][4];
#pragma unroll
    for (int i = 0; i < 4; i++)
#pragma unroll
        for (int j = 0; j < 4; j++) acc2[i][j] = 0ULL;

    for (int k0 = kbeg; k0 < kbeg + klen; k0 += 16) {
#pragma unroll
        for (int l = 0; l < 2; l++) {
            int lin = t + l * 128;        // 0..255
            int mm = lin & 63;
            int kk4 = lin >> 6;           // 0..3
            float4 av = *(const float4*)(d_g + ((size_t)mm * NN + (k0 >> 2) + kk4) * 48 + tq);
            As[kk4 * 4 + 0][mm] = av.x; As[kk4 * 4 + 1][mm] = av.y;
            As[kk4 * 4 + 2][mm] = av.z; As[kk4 * 4 + 3][mm] = av.w;
            float4 bv = *(const float4*)(B + (size_t)(n0 + mm) * K + k0 + kk4 * 4);
            Bs[kk4 * 4 + 0][mm] = bv.x; Bs[kk4 * 4 + 1][mm] = bv.y;
            Bs[kk4 * 4 + 2][mm] = bv.z; Bs[kk4 * 4 + 3][mm] = bv.w;
        }
        __syncthreads();
#pragma unroll
        for (int kk = 0; kk < 16; kk++) {
            float4 a = *(const float4*)&As[kk][ty * 4];
            ull ad0 = pack2(a.x, a.x), ad1 = pack2(a.y, a.y);
            ull ad2 = pack2(a.z, a.z), ad3 = pack2(a.w, a.w);
            const ull* bp = (const ull*)&Bs[kk][tx * 8];
            ull b0 = bp[0], b1 = bp[1], b2 = bp[2], b3 = bp[3];
            fma2(acc2[0][0], ad0, b0); fma2(acc2[0][1], ad0, b1);
            fma2(acc2[0][2], ad0, b2); fma2(acc2[0][3], ad0, b3);
            fma2(acc2[1][0], ad1, b0); fma2(acc2[1][1], ad1, b1);
            fma2(acc2[1][2], ad1, b2); fma2(acc2[1][3], ad1, b3);
            fma2(acc2[2][0], ad2, b0); fma2(acc2[2][1], ad2, b1);
            fma2(acc2[2][2], ad2, b2); fma2(acc2[2][3], ad2, b3);
            fma2(acc2[3][0], ad3, b0); fma2(acc2[3][1], ad3, b1);
            fma2(acc2[3][2], ad3, b2); fma2(acc2[3][3], ad3, b3);
        }
        __syncthreads();
    }
#pragma unroll
    for (int i = 0; i < 4; i++) {
        int m = m0 + ty * 4 + i;
        float* cr = d_xw1 + (size_t)m * N + n0 + tx * 8;
        float2 u0 = unpack2(acc2[i][0]), u1 = unpack2(acc2[i][1]);
        float2 u2 = unpack2(acc2[i][2]), u3 = unpack2(acc2[i][3]);
        redv4(cr,     u0.x, u0.y, u1.x, u1.y);
        redv4(cr + 4, u2.x, u2.y, u3.x, u3.y);
    }
}

// All three weight transposes in one kernel.
__global__ void k_transpose_all(const float* __restrict__ W1,
                                const float* __restrict__ W2,
                                const float* __restrict__ W3) {
    int idx = blockIdx.x * blockDim.x + threadIdx.x;
    if (idx < G1 * H1S) {                                   // whh1T
        int k = idx / G1, j = idx % G1;
        d_whh1T[idx] = W1[(size_t)j * H1S + k];
    } else if (idx < G1 * H1S + G2 * H2S) {                 // whh2T
        int r = idx - G1 * H1S;
        int k = r / G2, j = r % G2;
        d_whh2T[r] = W2[(size_t)j * H2S + k];
    } else if (idx < G1 * H1S + G2 * H2S + G2 * H1S) {      // wih2T
        int r = idx - G1 * H1S - G2 * H2S;
        int k = r / G2, j = r % G2;
        d_wih2T[r] = W3[(size_t)j * H1S + k];
    }
}

// ============ per-step LSTM kernels: gates + elementwise fused ============
__global__ __launch_bounds__(256) void k_step1(int t) {
    __shared__ __align__(16) float hs[H1S][16];
    __shared__ float gsm[64][17];
    int tid = threadIdx.x;
    int u0 = blockIdx.x * 16;
    int b0 = blockIdx.y * 16;
    for (int i = tid; i < H1S * 16; i += 256)
        hs[i >> 4][i & 15] = d_h1g[(i >> 4) * NB + b0 + (i & 15)];
    __syncthreads();

    int jj = tid & 63, bq = tid >> 6;
    int j = (jj >> 4) * H1S + u0 + (jj & 15);
    ull a01 = 0, a23 = 0;
    const float* wp = d_whh1T + j;
#pragma unroll 8
    for (int k = 0; k < H1S; k++) {
        float w = wp[k * G1];
        ull wd = pack2(w, w);
        const ull* hp = (const ull*)&hs[k][bq * 4];
        fma2(a01, wd, hp[0]);
        fma2(a23, wd, hp[1]);
    }
    {
        float2 u01 = unpack2(a01), u23 = unpack2(a23);
        float gv4[4] = {u01.x, u01.y, u23.x, u23.y};
#pragma unroll
        for (int i = 0; i < 4; i++) {
            int b = b0 + bq * 4 + i;
            gsm[jj][bq * 4 + i] = gv4[i] + d_xw1[((size_t)(t * NB + b)) * G1 + j];
        }
    }
    __syncthreads();
    {
        int bl = tid & 15, ul = tid >> 4;    // 16 units x 16 batches
        float iv = sigf(gsm[ul][bl]);
        float fv = sigf(gsm[16 + ul][bl]);
        float gv = tanhf(gsm[32 + ul][bl]);
        float ov = sigf(gsm[48 + ul][bl]);
        int ci = (u0 + ul) * NB + b0 + bl;
        float c = fv * d_c1g[ci] + iv * gv;
        d_c1g[ci] = c;
        d_h1g[ci] = ov * tanhf(c);
    }
}

__global__ __launch_bounds__(256) void k_step2(int t, const float* __restrict__ b2v) {
    __shared__ __align__(16) float h1s[H1S][16];
    __shared__ __align__(16) float h2s[H2S][16];
    __shared__ float gsm[64][17];
    int tid = threadIdx.x;
    int u0 = blockIdx.x * 16;
    int b0 = blockIdx.y * 16;
    for (int i = tid; i < H1S * 16; i += 256)
        h1s[i >> 4][i & 15] = d_h1g[(i >> 4) * NB + b0 + (i & 15)];
    for (int i = tid; i < H2S * 16; i += 256)
        h2s[i >> 4][i & 15] = d_h2g[(i >> 4) * NB + b0 + (i & 15)];
    __syncthreads();

    int jj = tid & 63, bq = tid >> 6;
    int j = (jj >> 4) * H2S + u0 + (jj & 15);
    ull a01 = 0, a23 = 0;
    const float* wp = d_wih2T + j;
#pragma unroll 8
    for (int k = 0; k < H1S; k++) {
        float w = wp[k * G2];
        ull wd = pack2(w, w);
        const ull* hp = (const ull*)&h1s[k][bq * 4];
        fma2(a01, wd, hp[0]);
        fma2(a23, wd, hp[1]);
    }
    const float* wq = d_whh2T + j;
#pragma unroll 8
    for (int k = 0; k < H2S; k++) {
        float w = wq[k * G2];
        ull wd = pack2(w, w);
        const ull* hp = (const ull*)&h2s[k][bq * 4];
        fma2(a01, wd, hp[0]);
        fma2(a23, wd, hp[1]);
    }
    {
        float bb = __ldg(b2v + j);
        float2 u01 = unpack2(a01), u23 = unpack2(a23);
        gsm[jj][bq * 4 + 0] = u01.x + bb;
        gsm[jj][bq * 4 + 1] = u01.y + bb;
        gsm[jj][bq * 4 + 2] = u23.x + bb;
        gsm[jj][bq * 4 + 3] = u23.y + bb;
    }
    __syncthreads();
    {
        int bl = tid & 15, ul = tid >> 4;
        float iv = sigf(gsm[ul][bl]);
        float fv = sigf(gsm[16 + ul][bl]);
        float gv = tanhf(gsm[32 + ul][bl]);
        float ov = sigf(gsm[48 + ul][bl]);
        int ci = (u0 + ul) * NB + b0 + bl;
        float c = fv * d_c2g[ci] + iv * gv;
        d_c2g[ci] = c;
        d_h2g[ci] = ov * tanhf(c);
    }
}

// out[b*2000 + j] = sum_k h2[k][b] * W_out[j,k] + b_out[j]
__global__ void k_out(const float* __restrict__ Wo, const float* __restrict__ bo,
                      float* __restrict__ out) {
    __shared__ __align__(16) float hr[H2S];
    int b = blockIdx.y;
    if (threadIdx.x < H2S) hr[threadIdx.x] = d_h2g[threadIdx.x * NB + b];
    __syncthreads();
    int j = blockIdx.x * blockDim.x + threadIdx.x;
    if (j >= NN * 2) return;
    const ull* wp = (const ull*)(Wo + (size_t)j * H2S);
    const ull* hp = (const ull*)hr;
    ull accA = 0, accB = 0;
#pragma unroll 8
    for (int k = 0; k < H2S / 2; k += 2) {
        fma2(accA, hp[k], wp[k]);
        fma2(accB, hp[k + 1], wp[k + 1]);
    }
    float2 uA = unpack2(accA), uB = unpack2(accB);
    out[(size_t)b * (NN * 2) + j] = uA.x + uA.y + uB.x + uB.y + __ldg(bo + j);
}

// ---------------- launch ----------------
extern "C" void kernel_launch(void* const* d_in, const int* in_sizes, int n_in,
                              void* d_out, int out_size) {
    const float* x     = (const float*)d_in[0];
    const int*   ei    = (const int*)d_in[1];     // int32 (JAX x64 disabled)
    const float* Wg    = (const float*)d_in[2];
    const float* att_s = (const float*)d_in[3];
    const float* att_d = (const float*)d_in[4];
    const float* gbias = (const float*)d_in[5];
    const float* Wih1  = (const float*)d_in[6];
    const float* Whh1  = (const float*)d_in[7];
    const float* b1    = (const float*)d_in[8];
    const float* Wih2  = (const float*)d_in[9];
    const float* Whh2  = (const float*)d_in[10];
    const float* b2    = (const float*)d_in[11];
    const float* Wo    = (const float*)d_in[12];
    const float* bo    = (const float*)d_in[13];
    float* out = (float*)d_out;

    int E = in_sizes[1] / 2;
    if (E > EMAX) E = EMAX;
    int etot = E + NTOT;

    // ncu captures launch #4 -> k_passC profiled this round.
    k_init<<<(NTOT * 48 + 255) / 256, 256>>>();                    // 1
    k_gemm_attn<<<NTOT / 64, 256>>>(x, Wg, att_s, att_d);          // 2
    k_passAB<<<(etot * 2 + 255) / 256, 256>>>(ei, E);              // 3
    k_passC<<<(etot * 12 + 255) / 256, 256>>>(ei, E);              // 4  <- profiled

    k_wsum<<<G1, 128>>>(Wih1);                                     // 5
    k_biasinit<<<(TBR * G1 + 255) / 256, 256>>>(b1, gbias);        // 6
    int ttot = G1 * H1S + G2 * H2S + G2 * H1S;
    k_transpose_all<<<(ttot + 255) / 256, 256>>>(Whh1, Whh2, Wih2);// 7

    k_sgemm1<<<dim3(G1 / 64, SEQL, SPLITK), 128>>>(Wih1);          // 8

    for (int t = 0; t < SEQL; t++) {
        k_step1<<<dim3(16, 4), 256>>>(t);
        k_step2<<<dim3(8, 4), 256>>>(t, b2);
    }
    k_out<<<dim3((NN * 2 + 255) / 256, NB), 256>>>(Wo, bo, out);
}

// round 14
// speedup vs baseline: 1.6948x; 1.2801x over previous
#include <cuda_runtime.h>
#include <math.h>

// ---------------- problem constants ----------------
#define NB    64        // batch
#define NN    1000      // nodes per sample
#define NTOT  64000     // NB*NN
#define SEQL  12
#define D1    4000      // NN*FEAT
#define H1S   256
#define H2S   128
#define G1    1024      // 4*H1S
#define G2    512       // 4*H2S
#define TBR   768       // SEQL*NB
#define EMAX  1024000
#define ETOTMAX (EMAX + NTOT)
#define SPLITK 10       // K=4000 -> klen=400, multiple of 16

typedef unsigned long long ull;

// ---------------- scratch (device globals; no allocation allowed) ----------------
__device__ __align__(256) float d_h[NTOT * 96];        // GAT hidden, [n][head][c]
__device__ __align__(256) float d_asrc[NTOT * 2];
__device__ __align__(256) float d_adst[NTOT * 2];
__device__ __align__(256) float d_den[NTOT * 2];       // segment sum of exp
__device__ __align__(256) float d_w[ETOTMAX * 2];      // softmax numerator exp(v)
__device__ __align__(256) float d_g[NTOT * 48];        // GAT output (head-mean, no bias)
__device__ __align__(256) float d_xw1[TBR * G1];       // LSTM1 input projection (no bias)
__device__ __align__(256) float d_whh1T[H1S * G1];
__device__ __align__(256) float d_whh2T[H2S * G2];
__device__ __align__(256) float d_wih2T[H1S * G2];
__device__ __align__(256) float d_ws[G1 * 4];          // col-sums of W_ih1 per (j, f)
// LSTM state block: [0,16384) h1 buf0 | [16384,32768) h1 buf1 |
// [32768,49152) c1 | [49152,57344) h2 | [57344,65536) c2   (all [unit][batch])
__device__ __align__(256) float d_state[65536];

// ---------------- helpers ----------------
__device__ __forceinline__ float sigf(float x) { return 1.f / (1.f + expf(-x)); }

// packed f32x2 FMA (FFMA2)
__device__ __forceinline__ void fma2(ull& acc, ull a, ull b) {
    asm("fma.rn.f32x2 %0, %1, %2, %0;" : "+l"(acc) : "l"(a), "l"(b));
}
__device__ __forceinline__ ull pack2(float x, float y) {
    ull r; asm("mov.b64 %0, {%1, %2};" : "=l"(r) : "f"(x), "f"(y)); return r;
}
__device__ __forceinline__ float2 unpack2(ull v) {
    float2 r; asm("mov.b64 {%0, %1}, %2;" : "=f"(r.x), "=f"(r.y) : "l"(v)); return r;
}
__device__ __forceinline__ void redv4(float* dst, float a, float b, float c, float d) {
    asm volatile("red.global.add.v4.f32 [%0], {%1, %2, %3, %4};"
                 :: "l"(dst), "f"(a), "f"(b), "f"(c), "f"(d) : "memory");
}
__device__ __forceinline__ void redv2(float* dst, float a, float b) {
    asm volatile("red.global.add.v2.f32 [%0], {%1, %2};"
                 :: "l"(dst), "f"(a), "f"(b) : "memory");
}

// ===== GAT projection (tiled GEMM) + attention coefficients + ALL zero-init =====
// Block: 64 nodes, all 96 output cols, K=48. 256 threads, 1000 blocks.
__global__ __launch_bounds__(256) void k_gemm_attn(
    const float* __restrict__ x, const float* __restrict__ Wg,
    const float* __restrict__ att_s, const float* __restrict__ att_d)
{
    __shared__ __align__(16) float xs[48][68];   // [k][node], padded stride
    __shared__ __align__(16) float ws[48][96];   // [k][col]
    __shared__ float als[96], ald[96];
    __shared__ float red1[64][17], red2[64][17];
    int tid = threadIdx.x;
    int n0 = blockIdx.x * 64;

    // ---- folded zero-init (replaces k_init / biasinit zeroing) ----
    for (int i = tid; i < 64 * 48; i += 256) d_g[(size_t)n0 * 48 + i] = 0.f;
    if (tid < 128) d_den[n0 * 2 + tid] = 0.f;
    if (blockIdx.x < TBR)
        for (int i = tid; i < G1; i += 256) d_xw1[(size_t)blockIdx.x * G1 + i] = 0.f;
    if (blockIdx.x >= 900)
        for (int i = (blockIdx.x - 900) * 256 + tid; i < 65536; i += 100 * 256)
            d_state[i] = 0.f;

    for (int i = tid; i < 48 * 96 / 4; i += 256) {
        float4 v = ((const float4*)Wg)[i];
        int k = i / 24, j = (i % 24) * 4;
        *(float4*)&ws[k][j] = v;
    }
    if (tid < 96) { als[tid] = __ldg(att_s + tid); ald[tid] = __ldg(att_d + tid); }
    for (int i = tid; i < 64 * 12; i += 256) {
        int node = i / 12, kq = i % 12;
        float4 v = ((const float4*)(x + (size_t)(n0 + node) * 48))[kq];
        xs[kq * 4 + 0][node] = v.x; xs[kq * 4 + 1][node] = v.y;
        xs[kq * 4 + 2][node] = v.z; xs[kq * 4 + 3][node] = v.w;
    }
    __syncthreads();

    int tx = tid & 15, ty = tid >> 4;
    int c0 = tx * 6;
    ull acc[4][3];
#pragma unroll
    for (int i = 0; i < 4; i++)
#pragma unroll
        for (int p = 0; p < 3; p++) acc[i][p] = 0ULL;

#pragma unroll 4
    for (int k = 0; k < 48; k++) {
        float4 a = *(const float4*)&xs[k][ty * 4];
        const ull* bp = (const ull*)&ws[k][c0];
        ull b0 = bp[0], b1 = bp[1], b2 = bp[2];
        ull a0 = pack2(a.x, a.x), a1 = pack2(a.y, a.y);
        ull a2 = pack2(a.z, a.z), a3 = pack2(a.w, a.w);
        fma2(acc[0][0], a0, b0); fma2(acc[0][1], a0, b1); fma2(acc[0][2], a0, b2);
        fma2(acc[1][0], a1, b0); fma2(acc[1][1], a1, b1); fma2(acc[1][2], a1, b2);
        fma2(acc[2][0], a2, b0); fma2(acc[2][1], a2, b1); fma2(acc[2][2], a2, b2);
        fma2(acc[3][0], a3, b0); fma2(acc[3][1], a3, b1); fma2(acc[3][2], a3, b2);
    }

#pragma unroll
    for (int i = 0; i < 4; i++) {
        int node = ty * 4 + i;
        float s1 = 0.f, s2 = 0.f;
#pragma unroll
        for (int p = 0; p < 3; p++) {
            float2 hv = unpack2(acc[i][p]);
            int c = c0 + p * 2;
            s1 = fmaf(hv.x, als[c], fmaf(hv.y, als[c + 1], s1));
            s2 = fmaf(hv.x, ald[c], fmaf(hv.y, ald[c + 1], s2));
            *(float2*)(d_h + (size_t)(n0 + node) * 96 + c) = hv;
        }
        red1[node][tx] = s1;
        red2[node][tx] = s2;
    }
    __syncthreads();
    if (tid < 128) {
        int node = tid & 63, head = tid >> 6;
        float s1 = 0.f, s2 = 0.f;
#pragma unroll
        for (int q = 0; q < 8; q++) {
            s1 += red1[node][head * 8 + q];
            s2 += red2[node][head * 8 + q];
        }
        d_asrc[(size_t)(n0 + node) * 2 + head] = s1;
        d_adst[(size_t)(n0 + node) * 2 + head] = s2;
    }
}

// edge_index arrives as int32 (JAX x64 disabled)
__device__ __forceinline__ void edge_sd(const int* __restrict__ ei, int E, int e,
                                        int& s, int& d) {
    if (e < E) { s = ei[e]; d = ei[E + e]; }
    else       { s = e - E; d = s; }
}

// Softmax without max-subtraction (|v| <~ 1; exp(v)/sum(exp(v)) math-identical).
// One thread per edge, both heads; vector loads + red.v2.
__global__ void k_passAB(const int* __restrict__ ei, int E) {
    int e = blockIdx.x * blockDim.x + threadIdx.x;
    int etot = E + NTOT;
    if (e >= etot) return;
    int s, d; edge_sd(ei, E, e, s, d);
    float2 as = *(const float2*)(d_asrc + (size_t)s * 2);
    float2 ad = *(const float2*)(d_adst + (size_t)d * 2);
    float v0 = as.x + ad.x; v0 = v0 > 0.f ? v0 : 0.2f * v0;
    float v1 = as.y + ad.y; v1 = v1 > 0.f ? v1 : 0.2f * v1;
    float w0 = expf(v0), w1 = expf(v1);
    *(float2*)(d_w + (size_t)e * 2) = make_float2(w0, w1);
    redv2(d_den + (size_t)d * 2, w0, w1);
}

// g[dst, q*4:+4] += a0*h[src,0,...] + a1*h[src,1,...] ; norm 0.5/(den+eps) inline
__global__ void k_passC(const int* __restrict__ ei, int E) {
    int idx = blockIdx.x * blockDim.x + threadIdx.x;
    int etot = E + NTOT;
    if (idx >= etot * 12) return;
    int e = idx / 12, q = idx - e * 12;
    int s, d; edge_sd(ei, E, e, s, d);
    float2 a  = *(const float2*)(d_w + (size_t)e * 2);
    float2 dn = *(const float2*)(d_den + (size_t)d * 2);
    float a0 = a.x * __fdividef(0.5f, dn.x + 1e-16f);
    float a1 = a.y * __fdividef(0.5f, dn.y + 1e-16f);
    const float4 h0 = *(const float4*)(d_h + (size_t)s * 96 + q * 4);
    const float4 h1 = *(const float4*)(d_h + (size_t)s * 96 + 48 + q * 4);
    float vx = fmaf(a0, h0.x, a1 * h1.x);
    float vy = fmaf(a0, h0.y, a1 * h1.y);
    float vz = fmaf(a0, h0.z, a1 * h1.z);
    float vw = fmaf(a0, h0.w, a1 * h1.w);
    redv4(d_g + (size_t)d * 48 + q * 4, vx, vy, vz, vw);
}

// NT SGEMM, A read directly from d_g (reshape folded into indexing).
// C = d_xw1 (zeroed), split-K via blockIdx.z, red-v4 epilogue. Bias added in k_pipe.
__global__ void k_sgemm1(const float* __restrict__ B) {
    const int K = D1, N = G1;
    __shared__ __align__(16) float As[16][64];
    __shared__ __align__(16) float Bs[16][64];
    int t = threadIdx.x;
    int ty = t >> 3;              // 0..15
    int tx = t & 7;               // 0..7
    int tq = blockIdx.y * 4;      // time index * FEAT
    int m0 = blockIdx.y * 64;
    int n0 = blockIdx.x * 64;
    int klen = K / SPLITK;        // 400
    int kbeg = blockIdx.z * klen;

    ull acc2[4][4];
#pragma unroll
    for (int i = 0; i < 4; i++)
#pragma unroll
        for (int j = 0; j < 4; j++) acc2[i][j] = 0ULL;

    for (int k0 = kbeg; k0 < kbeg + klen; k0 += 16) {
#pragma unroll
        for (int l = 0; l < 2; l++) {
            int lin = t + l * 128;        // 0..255
            int mm = lin & 63;
            int kk4 = lin >> 6;           // 0..3
            float4 av = *(const float4*)(d_g + ((size_t)mm * NN + (k0 >> 2) + kk4) * 48 + tq);
            As[kk4 * 4 + 0][mm] = av.x; As[kk4 * 4 + 1][mm] = av.y;
            As[kk4 * 4 + 2][mm] = av.z; As[kk4 * 4 + 3][mm] = av.w;
            float4 bv = *(const float4*)(B + (size_t)(n0 + mm) * K + k0 + kk4 * 4);
            Bs[kk4 * 4 + 0][mm] = bv.x; Bs[kk4 * 4 + 1][mm] = bv.y;
            Bs[kk4 * 4 + 2][mm] = bv.z; Bs[kk4 * 4 + 3][mm] = bv.w;
        }
        __syncthreads();
#pragma unroll
        for (int kk = 0; kk < 16; kk++) {
            float4 a = *(const float4*)&As[kk][ty * 4];
            ull ad0 = pack2(a.x, a.x), ad1 = pack2(a.y, a.y);
            ull ad2 = pack2(a.z, a.z), ad3 = pack2(a.w, a.w);
            const ull* bp = (const ull*)&Bs[kk][tx * 8];
            ull b0 = bp[0], b1 = bp[1], b2 = bp[2], b3 = bp[3];
            fma2(acc2[0][0], ad0, b0); fma2(acc2[0][1], ad0, b1);
            fma2(acc2[0][2], ad0, b2); fma2(acc2[0][3], ad0, b3);
            fma2(acc2[1][0], ad1, b0); fma2(acc2[1][1], ad1, b1);
            fma2(acc2[1][2], ad1, b2); fma2(acc2[1][3], ad1, b3);
            fma2(acc2[2][0], ad2, b0); fma2(acc2[2][1], ad2, b1);
            fma2(acc2[2][2], ad2, b2); fma2(acc2[2][3], ad2, b3);
            fma2(acc2[3][0], ad3, b0); fma2(acc2[3][1], ad3, b1);
            fma2(acc2[3][2], ad3, b2); fma2(acc2[3][3], ad3, b3);
        }
        __syncthreads();
    }
#pragma unroll
    for (int i = 0; i < 4; i++) {
        int m = m0 + ty * 4 + i;
        float* cr = d_xw1 + (size_t)m * N + n0 + tx * 8;
        float2 u0 = unpack2(acc2[i][0]), u1 = unpack2(acc2[i][1]);
        float2 u2 = unpack2(acc2[i][2]), u3 = unpack2(acc2[i][3]);
        redv4(cr,     u0.x, u0.y, u1.x, u1.y);
        redv4(cr + 4, u2.x, u2.y, u3.x, u3.y);
    }
}

// Prep: W_ih1 col-sums (blocks < G1) + all three weight transposes (rest).
__global__ void k_prep(const float* __restrict__ Wih1, const float* __restrict__ W1,
                       const float* __restrict__ W2, const float* __restrict__ W3) {
    if (blockIdx.x < G1) {
        __shared__ float part[256];
        int j = blockIdx.x;
        const float* wr = Wih1 + (size_t)j * D1;
        float acc = 0.f;
        for (int e = threadIdx.x; e < D1; e += 256) acc += __ldg(wr + e);  // f = e&3 fixed
        part[threadIdx.x] = acc;
        __syncthreads();
        if (threadIdx.x < 4) {
            float s = 0.f;
            for (int i = threadIdx.x; i < 256; i += 4) s += part[i];
            d_ws[j * 4 + threadIdx.x] = s;
        }
        return;
    }
    int idx = (blockIdx.x - G1) * 256 + threadIdx.x;
    if (idx < G1 * H1S) {                                   // whh1T
        int k = idx / G1, j = idx % G1;
        d_whh1T[idx] = W1[(size_t)j * H1S + k];
    } else if (idx < G1 * H1S + G2 * H2S) {                 // whh2T
        int r = idx - G1 * H1S;
        int k = r / G2, j = r % G2;
        d_whh2T[r] = W2[(size_t)j * H2S + k];
    } else if (idx < G1 * H1S + G2 * H2S + G2 * H1S) {      // wih2T
        int r = idx - G1 * H1S - G2 * H2S;
        int k = r / G2, j = r % G2;
        d_wih2T[r] = W3[(size_t)j * H1S + k];
    }
}

// ============ pipelined LSTM: launch s runs step1(t=s) [blocks 0..63] and
// step2(t=s-1) [blocks 64..95] concurrently. h1 double-buffered by t parity. ====
__global__ __launch_bounds__(256) void k_pipe(
    int s, const float* __restrict__ b1, const float* __restrict__ gbias,
    const float* __restrict__ b2v)
{
    __shared__ __align__(16) float hs1[H1S][16];
    __shared__ __align__(16) float hs2[H2S][16];
    __shared__ float gsm[64][17];
    int tid = threadIdx.x;

    if (blockIdx.x < 64) {
        // ---------- layer 1, t = s ----------
        if (s >= SEQL) return;
        int t = s;
        int u0 = (blockIdx.x & 15) * 16;
        int b0 = (blockIdx.x >> 4) * 16;
        const float* hR = d_state + (t & 1) * (H1S * NB);
        float*       hW = d_state + ((t + 1) & 1) * (H1S * NB);
        float*       c1 = d_state + 2 * (H1S * NB);

        for (int i = tid; i < H1S * 16; i += 256)
            hs1[i >> 4][i & 15] = hR[(i >> 4) * NB + b0 + (i & 15)];
        __syncthreads();

        int jj = tid & 63, bq = tid >> 6;
        int j = (jj >> 4) * H1S + u0 + (jj & 15);
        ull a01 = 0, a23 = 0;
        const float* wp = d_whh1T + j;
#pragma unroll 8
        for (int k = 0; k < H1S; k++) {
            float w = wp[k * G1];
            ull wd = pack2(w, w);
            const ull* hp = (const ull*)&hs1[k][bq * 4];
            fma2(a01, wd, hp[0]);
            fma2(a23, wd, hp[1]);
        }
        {
            // bias = b1[j] + sum_f gbias[4t+f]*ws[j,f]  (replaces k_biasinit)
            float bias = __ldg(b1 + j);
            float4 wsv = *(const float4*)(d_ws + j * 4);
            float4 gb  = *(const float4*)(gbias + 4 * t);
            bias = fmaf(gb.x, wsv.x, fmaf(gb.y, wsv.y,
                   fmaf(gb.z, wsv.z, fmaf(gb.w, wsv.w, bias))));
            float2 u01 = unpack2(a01), u23 = unpack2(a23);
            float gv4[4] = {u01.x, u01.y, u23.x, u23.y};
#pragma unroll
            for (int i = 0; i < 4; i++) {
                int b = b0 + bq * 4 + i;
                gsm[jj][bq * 4 + i] = gv4[i] + bias
                                    + d_xw1[((size_t)(t * NB + b)) * G1 + j];
            }
        }
        __syncthreads();
        {
            int bl = tid & 15, ul = tid >> 4;
            float iv = sigf(gsm[ul][bl]);
            float fv = sigf(gsm[16 + ul][bl]);
            float gv = tanhf(gsm[32 + ul][bl]);
            float ov = sigf(gsm[48 + ul][bl]);
            int ci = (u0 + ul) * NB + b0 + bl;
            float c = fv * c1[ci] + iv * gv;
            c1[ci] = c;
            hW[ci] = ov * tanhf(c);
        }
    } else {
        // ---------- layer 2, t = s-1 ----------
        if (s < 1) return;
        int t = s - 1;
        int r = blockIdx.x - 64;
        int u0 = (r & 7) * 16;
        int b0 = (r >> 3) * 16;
        const float* h1v = d_state + ((t + 1) & 1) * (H1S * NB);
        float*       h2  = d_state + 3 * (H1S * NB);
        float*       c2  = d_state + 3 * (H1S * NB) + H2S * NB;

        for (int i = tid; i < H1S * 16; i += 256)
            hs1[i >> 4][i & 15] = h1v[(i >> 4) * NB + b0 + (i & 15)];
        for (int i = tid; i < H2S * 16; i += 256)
            hs2[i >> 4][i & 15] = h2[(i >> 4) * NB + b0 + (i & 15)];
        __syncthreads();

        int jj = tid & 63, bq = tid >> 6;
        int j = (jj >> 4) * H2S + u0 + (jj & 15);
        ull a01 = 0, a23 = 0;
        const float* wp = d_wih2T + j;
#pragma unroll 8
        for (int k = 0; k < H1S; k++) {
            float w = wp[k * G2];
            ull wd = pack2(w, w);
            const ull* hp = (const ull*)&hs1[k][bq * 4];
            fma2(a01, wd, hp[0]);
            fma2(a23, wd, hp[1]);
        }
        const float* wq = d_whh2T + j;
#pragma unroll 8
        for (int k = 0; k < H2S; k++) {
            float w = wq[k * G2];
            ull wd = pack2(w, w);
            const ull* hp = (const ull*)&hs2[k][bq * 4];
            fma2(a01, wd, hp[0]);
            fma2(a23, wd, hp[1]);
        }
        {
            float bb = __ldg(b2v + j);
            float2 u01 = unpack2(a01), u23 = unpack2(a23);
            gsm[jj][bq * 4 + 0] = u01.x + bb;
            gsm[jj][bq * 4 + 1] = u01.y + bb;
            gsm[jj][bq * 4 + 2] = u23.x + bb;
            gsm[jj][bq * 4 + 3] = u23.y + bb;
        }
        __syncthreads();
        {
            int bl = tid & 15, ul = tid >> 4;
            float iv = sigf(gsm[ul][bl]);
            float fv = sigf(gsm[16 + ul][bl]);
            float gv = tanhf(gsm[32 + ul][bl]);
            float ov = sigf(gsm[48 + ul][bl]);
            int ci = (u0 + ul) * NB + b0 + bl;
            float c = fv * c2[ci] + iv * gv;
            c2[ci] = c;
            h2[ci] = ov * tanhf(c);
        }
    }
}

// out[b*2000 + j] = sum_k h2[k][b] * W_out[j,k] + b_out[j]
__global__ void k_out(const float* __restrict__ Wo, const float* __restrict__ bo,
                      float* __restrict__ out) {
    __shared__ __align__(16) float hr[H2S];
    const float* h2 = d_state + 3 * (H1S * NB);
    int b = blockIdx.y;
    if (threadIdx.x < H2S) hr[threadIdx.x] = h2[threadIdx.x * NB + b];
    __syncthreads();
    int j = blockIdx.x * blockDim.x + threadIdx.x;
    if (j >= NN * 2) return;
    const ull* wp = (const ull*)(Wo + (size_t)j * H2S);
    const ull* hp = (const ull*)hr;
    ull accA = 0, accB = 0;
#pragma unroll 8
    for (int k = 0; k < H2S / 2; k += 2) {
        fma2(accA, hp[k], wp[k]);
        fma2(accB, hp[k + 1], wp[k + 1]);
    }
    float2 uA = unpack2(accA), uB = unpack2(accB);
    out[(size_t)b * (NN * 2) + j] = uA.x + uA.y + uB.x + uB.y + __ldg(bo + j);
}

// ---------------- launch ----------------
extern "C" void kernel_launch(void* const* d_in, const int* in_sizes, int n_in,
                              void* d_out, int out_size) {
    const float* x     = (const float*)d_in[0];
    const int*   ei    = (const int*)d_in[1];     // int32 (JAX x64 disabled)
    const float* Wg    = (const float*)d_in[2];
    const float* att_s = (const float*)d_in[3];
    const float* att_d = (const float*)d_in[4];
    const float* gbias = (const float*)d_in[5];
    const float* Wih1  = (const float*)d_in[6];
    const float* Whh1  = (const float*)d_in[7];
    const float* b1    = (const float*)d_in[8];
    const float* Wih2  = (const float*)d_in[9];
    const float* Whh2  = (const float*)d_in[10];
    const float* b2    = (const float*)d_in[11];
    const float* Wo    = (const float*)d_in[12];
    const float* bo    = (const float*)d_in[13];
    float* out = (float*)d_out;

    int E = in_sizes[1] / 2;
    if (E > EMAX) E = EMAX;
    int etot = E + NTOT;

    // ncu captures launch #4 -> k_sgemm1 profiled this round.
    k_gemm_attn<<<NTOT / 64, 256>>>(x, Wg, att_s, att_d);          // 1 (incl. zero-init)
    k_passAB<<<(etot + 255) / 256, 256>>>(ei, E);                  // 2
    k_passC<<<(etot * 12 + 255) / 256, 256>>>(ei, E);              // 3
    k_sgemm1<<<dim3(G1 / 64, SEQL, SPLITK), 128>>>(Wih1);          // 4  <- profiled

    int tblocks = (G1 * H1S + G2 * H2S + G2 * H1S + 255) / 256;
    k_prep<<<G1 + tblocks, 256>>>(Wih1, Whh1, Whh2, Wih2);         // 5

    for (int s = 0; s <= SEQL; s++)                                // 6..18
        k_pipe<<<96, 256>>>(s, b1, gbias, b2);

    k_out<<<dim3((NN * 2 + 255) / 256, NB), 256>>>(Wo, bo, out);   // 19
}